// round 11
// baseline (speedup 1.0000x reference)
#include <cuda_runtime.h>
#include <cuda_fp16.h>
#include <math.h>
#include <stdint.h>

#define BB 8
#define TT 5
#define HH 512
#define WW 512
#define HW (HH*WW)
#define MID 16
#define NPIX (BB*HW)

// ---------------- scratch (no allocation allowed) ----------------
__device__ float  g_acc[NPIX];                    // 8 MB
__device__ __half g_h1[(size_t)NPIX*MID];         // 67 MB (conv3 out / final in)
__device__ __half g_h2[(size_t)NPIX*MID];         // 67 MB (conv2 out / conv3 in)
__device__ double g_dsum, g_dssq;
__device__ float g_mean, g_inv;
__device__ float g_w1f[144], g_s1[16];
__device__ uint32_t g_wF2[1152];                  // B fragments (half2) conv2
__device__ uint32_t g_wF3[1152];                  // B fragments (half2) conv3
__device__ uint32_t g_wF4[384];                   // B fragments (half2) conv4 1x1 (48-co pad)
__device__ float g_s2[16], g_s3[16];

// ---------------- PTX helpers ----------------
__device__ __forceinline__ uint32_t s2u(const void* p) {
    uint32_t a;
    asm("{ .reg .u64 t; cvta.to.shared.u64 t, %1; cvt.u32.u64 %0, t; }" : "=r"(a) : "l"(p));
    return a;
}
__device__ __forceinline__ void cpasync16(uint32_t dst, const void* src) {
    asm volatile("cp.async.cg.shared.global [%0], [%1], 16;" :: "r"(dst), "l"(src));
}
__device__ __forceinline__ void cpasync4(uint32_t dst, const void* src) {
    asm volatile("cp.async.ca.shared.global [%0], [%1], 4;" :: "r"(dst), "l"(src));
}
__device__ __forceinline__ void cp_commit() {
    asm volatile("cp.async.commit_group;" ::: "memory");
}
template<int N> __device__ __forceinline__ void cp_wait() {
    asm volatile("cp.async.wait_group %0;" :: "n"(N) : "memory");
}
__device__ __forceinline__ void sts_zero16(uint32_t dst) {
    asm volatile("st.shared.v4.u32 [%0], {%1,%1,%1,%1};" :: "r"(dst), "r"(0u) : "memory");
}
__device__ __forceinline__ void sts_zero4(uint32_t dst) {
    asm volatile("st.shared.b32 [%0], %1;" :: "r"(dst), "r"(0u) : "memory");
}
__device__ __forceinline__ void sts128(uint32_t dst, uint32_t a, uint32_t b,
                                       uint32_t c, uint32_t d) {
    asm volatile("st.shared.v4.b32 [%0], {%1,%2,%3,%4};"
                 :: "r"(dst), "r"(a), "r"(b), "r"(c), "r"(d) : "memory");
}
__device__ __forceinline__ void ldmatrix_x4(uint32_t& r0, uint32_t& r1, uint32_t& r2,
                                            uint32_t& r3, uint32_t addr) {
    asm volatile("ldmatrix.sync.aligned.m8n8.x4.shared.b16 {%0,%1,%2,%3}, [%4];"
                 : "=r"(r0), "=r"(r1), "=r"(r2), "=r"(r3) : "r"(addr));
}
__device__ __forceinline__ void mma_f16(float* d, uint32_t a0, uint32_t a1, uint32_t a2,
                                        uint32_t a3, uint32_t b0, uint32_t b1) {
    asm volatile(
        "mma.sync.aligned.m16n8k16.row.col.f32.f16.f16.f32 "
        "{%0,%1,%2,%3}, {%4,%5,%6,%7}, {%8,%9}, {%0,%1,%2,%3};"
        : "+f"(d[0]), "+f"(d[1]), "+f"(d[2]), "+f"(d[3])
        : "r"(a0), "r"(a1), "r"(a2), "r"(a3), "r"(b0), "r"(b1));
}
__device__ __forceinline__ uint32_t pack_h2(float a, float b) {
    __half2 h = __floats2half2_rn(a, b);
    return *reinterpret_cast<uint32_t*>(&h);
}

// ---------------- prep ----------------
__global__ void prep_kernel(
    const float* __restrict__ w1, const float* __restrict__ g1, const float* __restrict__ b1,
    const float* __restrict__ rm1, const float* __restrict__ rv1,
    const float* __restrict__ w2, const float* __restrict__ g2, const float* __restrict__ b2,
    const float* __restrict__ rm2, const float* __restrict__ rv2,
    const float* __restrict__ w3, const float* __restrict__ g3, const float* __restrict__ b3,
    const float* __restrict__ rm3, const float* __restrict__ rv3,
    const float* __restrict__ w4)
{
    int tid = threadIdx.x;
    if (tid == 0) { g_dsum = 0.0; g_dssq = 0.0; }

    for (int i = tid; i < 144; i += 256) {
        int o = i / 9, k = i % 9;
        float sc = g1[o] / sqrtf(rv1[o] + 1e-5f);
        float s = 0.f;
        #pragma unroll
        for (int t = 0; t < TT; t++) s += w1[(o * TT + t) * 9 + k];
        g_w1f[i] = sc * s;
    }
    if (tid < 16) {
        float sc1 = g1[tid] / sqrtf(rv1[tid] + 1e-5f);
        g_s1[tid] = b1[tid] - rm1[tid] * sc1;
        float sc2 = g2[tid] / sqrtf(rv2[tid] + 1e-5f);
        g_s2[tid] = b2[tid] - rm2[tid] * sc2;
        float sc3 = g3[tid] / sqrtf(rv3[tid] + 1e-5f);
        g_s3[tid] = b3[tid] - rm3[tid] * sc3;
    }
    for (int i = tid; i < 1152; i += 256) {
        int t = i & 31, r = (i >> 5) & 1, g = (i >> 6) & 1, tap = i >> 7;
        int co = (g << 3) + (t >> 2);
        int k0 = (t & 3) * 2 + (r << 3);
        float sc2 = g2[co] / sqrtf(rv2[co] + 1e-5f);
        g_wF2[i] = pack_h2(sc2 * w2[((co * 16 + k0) * 9) + tap],
                           sc2 * w2[((co * 16 + k0 + 1) * 9) + tap]);
        float sc3 = g3[co] / sqrtf(rv3[co] + 1e-5f);
        g_wF3[i] = pack_h2(sc3 * w3[((co * 16 + k0) * 9) + tap],
                           sc3 * w3[((co * 16 + k0 + 1) * 9) + tap]);
    }
    for (int i = tid; i < 384; i += 256) {
        int t = i & 31, r = (i >> 5) & 1, n = i >> 6;
        int co = (n << 3) + (t >> 2);
        int k0 = (t & 3) * 2 + (r << 3);
        float v0 = (co < 45) ? w4[co * 16 + k0]     : 0.f;
        float v1 = (co < 45) ? w4[co * 16 + k0 + 1] : 0.f;
        g_wF4[i] = pack_h2(v0, v1);
    }
}

// ---------------- acc = sum|raw_diff| + mean/var reduction ----------------
__global__ void accum_kernel(const float* __restrict__ rd)
{
    int i = blockIdx.x * 256 + threadIdx.x;
    int b = i >> 16;
    int r = i & 65535;
    const float4* p = (const float4*)rd;
    float4 a = make_float4(0.f, 0.f, 0.f, 0.f);
    #pragma unroll
    for (int t = 0; t < TT - 1; t++) {
        float4 v = p[((size_t)(b * (TT - 1) + t)) * 65536 + r];
        a.x += fabsf(v.x); a.y += fabsf(v.y); a.z += fabsf(v.z); a.w += fabsf(v.w);
    }
    ((float4*)g_acc)[i] = a;

    double ls  = (double)a.x + (double)a.y + (double)a.z + (double)a.w;
    double lss = (double)a.x * a.x + (double)a.y * a.y + (double)a.z * a.z + (double)a.w * a.w;
    #pragma unroll
    for (int o = 16; o > 0; o >>= 1) {
        ls  += __shfl_down_sync(0xffffffffu, ls,  o);
        lss += __shfl_down_sync(0xffffffffu, lss, o);
    }
    __shared__ double ss[8], sq[8];
    int wid = threadIdx.x >> 5, lane = threadIdx.x & 31;
    if (lane == 0) { ss[wid] = ls; sq[wid] = lss; }
    __syncthreads();
    if (threadIdx.x == 0) {
        double s = 0.0, q = 0.0;
        #pragma unroll
        for (int w = 0; w < 8; w++) { s += ss[w]; q += sq[w]; }
        atomicAdd(&g_dsum, s);
        atomicAdd(&g_dssq, q);
    }
}

__global__ void finalize_kernel()
{
    double n = (double)NPIX;
    double mean = g_dsum / n;
    double var = (g_dssq - g_dsum * g_dsum / n) / (n - 1.0);
    double sd = sqrt(var);
    g_mean = (float)mean;
    g_inv = (float)(1.0 / (sd + 1e-6));
}

// ---------------- fused conv1+conv2 (DIL=2): acc -> h1(on-the-fly, smem) -> HMMA -> g_h2 ----
// CTA: 128-px strip x 64 rows, 256 threads. h ring produced in-CTA from acc ring.
__global__ __launch_bounds__(256) void conv12_fused_kernel()
{
    constexpr int DIL = 2, XW = 128, YR = 64;
    constexpr int RING = 7, SEGPX = XW + 2 * DIL;          // 132 px
    constexpr int SLOTB = SEGPX * 48;                      // 6336 B
    constexpr int RINGA = 10, ASEG = XW + 2 * DIL + 2;     // 134 px
    constexpr int ASLOT = 544;                             // 136 f, 16B-mult
    constexpr int W1OFF = RINGA * ASLOT;                   // 5440
    constexpr int HOFF  = W1OFF + 832;                     // 6272 (16B aligned)

    extern __shared__ char smem[];
    uint32_t sbase = s2u(smem);
    float* sw1 = (float*)(smem + W1OFF);                   // [16][12] padded
    float* sb1 = (float*)(smem + W1OFF + 768);             // [16]
    int tid = threadIdx.x;
    int warp = tid >> 5, lane = tid & 31;
    int x0 = blockIdx.x * XW;
    int y0 = blockIdx.y * YR;
    int b  = blockIdx.z;
    const float* accb = g_acc + ((size_t)b << 18);
    __half* out = g_h2;

    // conv1 weights -> padded smem
    for (int i = tid; i < 192; i += 256) {
        int o = i / 12, k = i % 12;
        sw1[i] = (k < 9) ? g_w1f[o * 9 + k] : 0.f;
    }
    if (tid < 16) sb1[tid] = g_s1[tid];
    float mean = g_mean, inv = g_inv;

    // conv2 B fragments + bias -> registers
    uint32_t bw[9][2][2];
    #pragma unroll
    for (int tap = 0; tap < 9; tap++)
        #pragma unroll
        for (int g = 0; g < 2; g++)
            #pragma unroll
            for (int r = 0; r < 2; r++)
                bw[tap][g][r] = g_wF2[(((tap << 1) + g) << 1 | r) * 32 + lane];
    float bc0[2], bc1[2];
    #pragma unroll
    for (int g = 0; g < 2; g++) {
        int c = (g << 3) + ((lane & 3) << 1);
        bc0[g] = g_s2[c]; bc1[g] = g_s2[c + 1];
    }
    int prow = warp * 16 + (lane & 7) + ((lane >> 3) & 1) * 8;
    int sel16 = ((lane >> 4) & 1) * 16;

    auto load_acc = [&](int r) {
        if (r >= 0 && r < HH && r <= y0 + YR + 2) {
            uint32_t dbase = sbase + ((r - (y0 - 3)) % RINGA) * ASLOT;
            const float* arow = accb + ((size_t)r << 9);
            for (int u = tid; u < ASEG; u += 256) {
                int x = x0 - 3 + u;
                uint32_t dst = dbase + u * 4;
                if ((unsigned)x < (unsigned)WW) cpasync4(dst, arow + x);
                else                            sts_zero4(dst);
            }
        }
        cp_commit();
    };

    auto produce_h = [&](int r) {
        if (r > y0 + YR - 1 + DIL) return;
        int slot = (r - (y0 - DIL)) % RING;
        uint32_t hbase = sbase + HOFF + slot * SLOTB;
        bool rowok = (r >= 0) & (r < HH);
        for (int u = tid; u < SEGPX * 2; u += 256) {
            int s = u >> 1, half = u & 1;
            int x = x0 - DIL + s;
            uint32_t dst = hbase + s * 48 + half * 16;
            if (!rowok || (unsigned)x >= (unsigned)WW) { sts_zero16(dst); continue; }
            float av[9];
            #pragma unroll
            for (int ky = 0; ky < 3; ky++) {
                int rr = r - 1 + ky;
                bool rv = (rr >= 0) & (rr < HH);
                const float* aseg = (const float*)(smem + ((rr - (y0 - 3)) % RINGA) * ASLOT);
                #pragma unroll
                for (int kx = 0; kx < 3; kx++) {
                    int xx = x - 1 + kx;
                    bool ok = rv & ((unsigned)xx < (unsigned)WW);
                    float raw = aseg[s + kx];
                    av[ky * 3 + kx] = ok ? (raw - mean) * inv : 0.f;
                }
            }
            uint32_t pk[4];
            #pragma unroll
            for (int j = 0; j < 4; j++) {
                int o = half * 8 + j * 2;
                const float* w0 = sw1 + o * 12;
                const float* w1p = sw1 + (o + 1) * 12;
                float s0 = sb1[o], s1v = sb1[o + 1];
                #pragma unroll
                for (int k = 0; k < 9; k++) {
                    s0  = fmaf(w0[k],  av[k], s0);
                    s1v = fmaf(w1p[k], av[k], s1v);
                }
                pk[j] = pack_h2(fmaxf(s0, 0.f), fmaxf(s1v, 0.f));
            }
            sts128(dst, pk[0], pk[1], pk[2], pk[3]);
        }
    };

    // prologue: acc rows y0-3 .. y0+5; produce h rows y0-2 .. y0+2
    for (int r = y0 - 3; r <= y0 + 5; r++) load_acc(r);
    cp_wait<2>();
    __syncthreads();
    for (int r = y0 - 2; r <= y0 + 2; r++) produce_h(r);
    __syncthreads();

    for (int i = 0; i < YR; i++) {
        int y = y0 + i;
        load_acc(y + 6);
        cp_wait<2>();
        __syncthreads();               // acc(y+4) ready; h rows <= y+2 published

        produce_h(y + 3);              // writes slot disjoint from MMA reads below

        float d[2][4];
        #pragma unroll
        for (int g = 0; g < 2; g++)
            #pragma unroll
            for (int r2 = 0; r2 < 4; r2++) d[g][r2] = 0.f;

        #pragma unroll
        for (int ky = 0; ky < 3; ky++) {
            uint32_t abase = sbase + HOFF + ((i + ky * DIL) % RING) * SLOTB;
            #pragma unroll
            for (int kx = 0; kx < 3; kx++) {
                uint32_t a0, a1, a2, a3;
                ldmatrix_x4(a0, a1, a2, a3, abase + (prow + kx * DIL) * 48 + sel16);
                int tap = ky * 3 + kx;
                mma_f16(d[0], a0, a1, a2, a3, bw[tap][0][0], bw[tap][0][1]);
                mma_f16(d[1], a0, a1, a2, a3, bw[tap][1][0], bw[tap][1][1]);
            }
        }

        __half* orow = out + ((((size_t)b << 18) + ((size_t)y << 9) + x0 + warp * 16)) * 16;
        int px = (lane >> 2);
        #pragma unroll
        for (int g = 0; g < 2; g++) {
            int c = (g << 3) + ((lane & 3) << 1);
            uint32_t lo = pack_h2(fmaxf(d[g][0] + bc0[g], 0.f), fmaxf(d[g][1] + bc1[g], 0.f));
            uint32_t hi = pack_h2(fmaxf(d[g][2] + bc0[g], 0.f), fmaxf(d[g][3] + bc1[g], 0.f));
            *(uint32_t*)(orow + px * 16 + c)       = lo;
            *(uint32_t*)(orow + (px + 8) * 16 + c) = hi;
        }
    }
}

// ---------------- conv3 via ldmatrix + mma.sync (unchanged, DIL=4) ----------------
template<int DIL>
__global__ __launch_bounds__(256) void conv16_hmma_kernel()
{
    constexpr int XW = 128, YR = 64, PD = 2;
    constexpr int RING = 2 * DIL + PD + 1;
    constexpr int SEGPX = XW + 2 * DIL;
    constexpr int SLOTB = SEGPX * 48;

    const __half* __restrict__ in  = (DIL == 2) ? g_h1 : g_h2;
    __half*       __restrict__ out = (DIL == 2) ? g_h2 : g_h1;
    const uint32_t* __restrict__ wF = (DIL == 2) ? g_wF2 : g_wF3;
    const float* __restrict__ sB   = (DIL == 2) ? g_s2  : g_s3;

    extern __shared__ char smem[];
    uint32_t sbase = s2u(smem);
    int tid = threadIdx.x;
    int warp = tid >> 5, lane = tid & 31;
    int x0 = blockIdx.x * XW;
    int y0 = blockIdx.y * YR;
    int b  = blockIdx.z;
    const __half* gin = in + (((size_t)b) << 18) * 16;

    uint32_t bw[9][2][2];
    #pragma unroll
    for (int tap = 0; tap < 9; tap++)
        #pragma unroll
        for (int g = 0; g < 2; g++)
            #pragma unroll
            for (int r = 0; r < 2; r++)
                bw[tap][g][r] = wF[(((tap << 1) + g) << 1 | r) * 32 + lane];

    float bc0[2], bc1[2];
    #pragma unroll
    for (int g = 0; g < 2; g++) {
        int c = (g << 3) + ((lane & 3) << 1);
        bc0[g] = sB[c]; bc1[g] = sB[c + 1];
    }

    int prow = warp * 16 + (lane & 7) + ((lane >> 3) & 1) * 8;
    int sel16 = ((lane >> 4) & 1) * 16;

    auto load_row = [&](int idx) {
        if (idx <= YR - 1 + 2 * DIL) {
            int r = y0 - DIL + idx;
            uint32_t dbase = sbase + (idx % RING) * SLOTB;
            bool rok = (r >= 0) & (r < HH);
            const __half* grow = gin + (((size_t)r) << 9) * 16;
            for (int c = tid; c < SEGPX * 2; c += 256) {
                int s = c >> 1, part = c & 1;
                int x = x0 - DIL + s;
                uint32_t dst = dbase + s * 48 + part * 16;
                if (rok && (unsigned)x < (unsigned)WW)
                    cpasync16(dst, grow + x * 16 + part * 8);
                else
                    sts_zero16(dst);
            }
        }
        cp_commit();
    };

    for (int idx = 0; idx <= 2 * DIL + PD; idx++) load_row(idx);

    for (int i = 0; i < YR; i++) {
        cp_wait<PD>();
        __syncthreads();

        float d[2][4];
        #pragma unroll
        for (int g = 0; g < 2; g++)
            #pragma unroll
            for (int r = 0; r < 4; r++) d[g][r] = 0.f;

        #pragma unroll
        for (int ky = 0; ky < 3; ky++) {
            uint32_t abase = sbase + ((i + ky * DIL) % RING) * SLOTB;
            #pragma unroll
            for (int kx = 0; kx < 3; kx++) {
                uint32_t a0, a1, a2, a3;
                ldmatrix_x4(a0, a1, a2, a3, abase + (prow + kx * DIL) * 48 + sel16);
                int tap = ky * 3 + kx;
                mma_f16(d[0], a0, a1, a2, a3, bw[tap][0][0], bw[tap][0][1]);
                mma_f16(d[1], a0, a1, a2, a3, bw[tap][1][0], bw[tap][1][1]);
            }
        }

        __half* orow = out + ((((size_t)b << 18) + ((size_t)(y0 + i) << 9) + x0 + warp * 16)) * 16;
        int px = (lane >> 2);
        #pragma unroll
        for (int g = 0; g < 2; g++) {
            int c = (g << 3) + ((lane & 3) << 1);
            uint32_t lo = pack_h2(fmaxf(d[g][0] + bc0[g], 0.f), fmaxf(d[g][1] + bc1[g], 0.f));
            uint32_t hi = pack_h2(fmaxf(d[g][2] + bc0[g], 0.f), fmaxf(d[g][3] + bc1[g], 0.f));
            *(uint32_t*)(orow + px * 16 + c)       = lo;
            *(uint32_t*)(orow + (px + 8) * 16 + c) = hi;
        }

        __syncthreads();
        load_row(i + 2 * DIL + PD + 1);
    }
}

// ---------------- final: conv4 1x1 HMMA + sigmoid + vectorized dyn filtering ----------------
__global__ __launch_bounds__(320) void final_mma_kernel(
    const float* __restrict__ x, const float* __restrict__ biasp,
    float* __restrict__ out)
{
    extern __shared__ float sker[];    // 64*5*44 floats

    int tid = threadIdx.x;
    int warp = tid >> 5, lane = tid & 31;
    int pbase = blockIdx.x * 256;
    int b = pbase >> 18;
    int rem = pbase & (HW - 1);
    int y = rem >> 9, xb0 = rem & 511;

    if (warp < 8) {
        uint32_t bw[6][2];
        #pragma unroll
        for (int n = 0; n < 6; n++) {
            bw[n][0] = g_wF4[(n * 2 + 0) * 32 + lane];
            bw[n][1] = g_wF4[(n * 2 + 1) * 32 + lane];
        }
        float bias = biasp[0];
        int arow = lane >> 2;
        int cc = (lane & 3) * 2;

        #pragma unroll
        for (int tt = 0; tt < 2; tt++) {
            int tpx = warp * 32 + tt * 16;
            const __half* hb = g_h1 + (size_t)(pbase + tpx) * 16;
            uint32_t a0 = *(const uint32_t*)(hb + arow * 16 + cc);
            uint32_t a1 = *(const uint32_t*)(hb + (arow + 8) * 16 + cc);
            uint32_t a2 = *(const uint32_t*)(hb + arow * 16 + cc + 8);
            uint32_t a3 = *(const uint32_t*)(hb + (arow + 8) * 16 + cc + 8);

            float d[6][4];
            #pragma unroll
            for (int n = 0; n < 6; n++)
                #pragma unroll
                for (int r = 0; r < 4; r++) d[n][r] = 0.f;
            #pragma unroll
            for (int n = 0; n < 6; n++)
                mma_f16(d[n], a0, a1, a2, a3, bw[n][0], bw[n][1]);

            #pragma unroll
            for (int n = 0; n < 6; n++) {
                int c0 = n * 8 + cc;
                int t0 = c0 / 9,       tap0 = c0 - t0 * 9;
                int t1 = (c0 + 1) / 9, tap1 = (c0 + 1) - t1 * 9;
                #pragma unroll
                for (int half = 0; half < 2; half++) {
                    int px = tpx + arow + half * 8;
                    int base = ((px >> 2) * 5);
                    int sub = (px & 3) * 9;
                    float z0 = d[n][half * 2 + 0] + bias;
                    float z1 = d[n][half * 2 + 1] + bias;
                    float k0 = fmaf(10.f, 1.f / (1.f + __expf(-z0)), 0.1f);
                    float k1 = fmaf(10.f, 1.f / (1.f + __expf(-z1)), 0.1f);
                    if (c0 < 45)     sker[(base + t0) * 44 + sub + tap0] = k0;
                    if (c0 + 1 < 45) sker[(base + t1) * 44 + sub + tap1] = k1;
                }
            }
        }
    }
    __syncthreads();

    int q = tid & 63;
    int tp = tid >> 6;
    int x0 = xb0 + q * 4;

    float w[36];
    const float4* kp = (const float4*)(sker + (q * 5 + tp) * 44);
    #pragma unroll
    for (int j = 0; j < 9; j++) {
        float4 f = kp[j];
        w[j * 4 + 0] = f.x; w[j * 4 + 1] = f.y; w[j * 4 + 2] = f.z; w[j * 4 + 3] = f.w;
    }

    const float* xp = x + ((size_t)(b * TT + tp) << 18);
    float o0 = 0.f, o1 = 0.f, o2 = 0.f, o3 = 0.f;
    #pragma unroll
    for (int dy = 0; dy < 3; dy++) {
        int yy = y + dy - 1;
        if ((unsigned)yy >= (unsigned)HH) continue;
        const float* row = xp + (yy << 9);
        float v[6];
        v[0] = (x0 > 0) ? row[x0 - 1] : 0.f;
        float4 mm = *(const float4*)(row + x0);
        v[1] = mm.x; v[2] = mm.y; v[3] = mm.z; v[4] = mm.w;
        v[5] = (x0 + 4 < WW) ? row[x0 + 4] : 0.f;
        #pragma unroll
        for (int dx = 0; dx < 3; dx++) {
            int j = dy * 3 + dx;
            o0 = fmaf(w[0 * 9 + j], v[dx],     o0);
            o1 = fmaf(w[1 * 9 + j], v[dx + 1], o1);
            o2 = fmaf(w[2 * 9 + j], v[dx + 2], o2);
            o3 = fmaf(w[3 * 9 + j], v[dx + 3], o3);
        }
    }
    *(float4*)(out + ((size_t)(b * TT + tp) << 18) + (y << 9) + x0) =
        make_float4(o0, o1, o2, o3);
}

// ---------------- launch ----------------
extern "C" void kernel_launch(void* const* d_in, const int* in_sizes, int n_in,
                              void* d_out, int out_size)
{
    const float* x_aligned = (const float*)d_in[0];
    const float* raw_diff  = (const float*)d_in[1];
    const float* w1  = (const float*)d_in[2];
    const float* g1  = (const float*)d_in[3];
    const float* b1  = (const float*)d_in[4];
    const float* rm1 = (const float*)d_in[5];
    const float* rv1 = (const float*)d_in[6];
    const float* w2  = (const float*)d_in[7];
    const float* g2  = (const float*)d_in[8];
    const float* b2  = (const float*)d_in[9];
    const float* rm2 = (const float*)d_in[10];
    const float* rv2 = (const float*)d_in[11];
    const float* w3  = (const float*)d_in[12];
    const float* g3  = (const float*)d_in[13];
    const float* b3  = (const float*)d_in[14];
    const float* rm3 = (const float*)d_in[15];
    const float* rv3 = (const float*)d_in[16];
    const float* w4  = (const float*)d_in[17];
    const float* bias = (const float*)d_in[18];
    float* out = (float*)d_out;

    const int SMEM12 = 6272 + 7 * (132 * 48);   // 50,624 B
    const int SMEM4  = 11 * (136 * 48);         // 71,808 B
    const int SMEMF  = 64 * 5 * 44 * 4;         // 56,320 B
    static bool attr_done = false;
    if (!attr_done) {
        cudaFuncSetAttribute(conv12_fused_kernel,   cudaFuncAttributeMaxDynamicSharedMemorySize, SMEM12);
        cudaFuncSetAttribute(conv16_hmma_kernel<4>, cudaFuncAttributeMaxDynamicSharedMemorySize, SMEM4);
        cudaFuncSetAttribute(final_mma_kernel,      cudaFuncAttributeMaxDynamicSharedMemorySize, SMEMF);
        attr_done = true;
    }

    prep_kernel<<<1, 256>>>(w1, g1, b1, rm1, rv1, w2, g2, b2, rm2, rv2,
                            w3, g3, b3, rm3, rv3, w4);
    accum_kernel<<<NPIX / 4 / 256, 256>>>(raw_diff);
    finalize_kernel<<<1, 1>>>();
    {
        dim3 grd(WW / 128, HH / 64, BB);   // (4, 8, 8)
        conv12_fused_kernel<<<grd, 256, SMEM12>>>();
        conv16_hmma_kernel<4><<<grd, 256, SMEM4>>>();
    }
    final_mma_kernel<<<NPIX / 256, 320, SMEMF>>>(x_aligned, bias, out);
}

// round 12
// speedup vs baseline: 1.2265x; 1.2265x over previous
#include <cuda_runtime.h>
#include <cuda_fp16.h>
#include <math.h>
#include <stdint.h>

#define BB 8
#define TT 5
#define HH 512
#define WW 512
#define HW (HH*WW)
#define MID 16
#define NPIX (BB*HW)

// ---------------- scratch (no allocation allowed) ----------------
__device__ float  g_acc[NPIX];                    // 8 MB
__device__ __half g_h1[(size_t)NPIX*MID];         // 67 MB
__device__ __half g_h2[(size_t)NPIX*MID];         // 67 MB
__device__ double g_dsum, g_dssq;
__device__ float g_mean, g_inv;
__device__ float g_w1f[144], g_s1[16];
__device__ uint32_t g_wF2[1152];                  // B fragments (half2) conv2
__device__ uint32_t g_wF3[1152];                  // B fragments (half2) conv3
__device__ uint32_t g_wF4[384];                   // B fragments (half2) conv4 1x1 (48-co pad)
__device__ float g_s2[16], g_s3[16];

// ---------------- PTX helpers ----------------
__device__ __forceinline__ uint32_t s2u(const void* p) {
    uint32_t a;
    asm("{ .reg .u64 t; cvta.to.shared.u64 t, %1; cvt.u32.u64 %0, t; }" : "=r"(a) : "l"(p));
    return a;
}
__device__ __forceinline__ void cpasync16(uint32_t dst, const void* src) {
    asm volatile("cp.async.cg.shared.global [%0], [%1], 16;" :: "r"(dst), "l"(src));
}
__device__ __forceinline__ void cp_commit() {
    asm volatile("cp.async.commit_group;" ::: "memory");
}
template<int N> __device__ __forceinline__ void cp_wait() {
    asm volatile("cp.async.wait_group %0;" :: "n"(N) : "memory");
}
__device__ __forceinline__ void sts_zero16(uint32_t dst) {
    asm volatile("st.shared.v4.u32 [%0], {%1,%1,%1,%1};" :: "r"(dst), "r"(0u) : "memory");
}
__device__ __forceinline__ void ldmatrix_x4(uint32_t& r0, uint32_t& r1, uint32_t& r2,
                                            uint32_t& r3, uint32_t addr) {
    asm volatile("ldmatrix.sync.aligned.m8n8.x4.shared.b16 {%0,%1,%2,%3}, [%4];"
                 : "=r"(r0), "=r"(r1), "=r"(r2), "=r"(r3) : "r"(addr));
}
__device__ __forceinline__ void mma_f16(float* d, uint32_t a0, uint32_t a1, uint32_t a2,
                                        uint32_t a3, uint32_t b0, uint32_t b1) {
    asm volatile(
        "mma.sync.aligned.m16n8k16.row.col.f32.f16.f16.f32 "
        "{%0,%1,%2,%3}, {%4,%5,%6,%7}, {%8,%9}, {%0,%1,%2,%3};"
        : "+f"(d[0]), "+f"(d[1]), "+f"(d[2]), "+f"(d[3])
        : "r"(a0), "r"(a1), "r"(a2), "r"(a3), "r"(b0), "r"(b1));
}
__device__ __forceinline__ uint32_t pack_h2(float a, float b) {
    __half2 h = __floats2half2_rn(a, b);
    return *reinterpret_cast<uint32_t*>(&h);
}

// ---------------- prep: fold BN into conv weights, build B fragments ----------------
__global__ void prep_kernel(
    const float* __restrict__ w1, const float* __restrict__ g1, const float* __restrict__ b1,
    const float* __restrict__ rm1, const float* __restrict__ rv1,
    const float* __restrict__ w2, const float* __restrict__ g2, const float* __restrict__ b2,
    const float* __restrict__ rm2, const float* __restrict__ rv2,
    const float* __restrict__ w3, const float* __restrict__ g3, const float* __restrict__ b3,
    const float* __restrict__ rm3, const float* __restrict__ rv3,
    const float* __restrict__ w4)
{
    int tid = threadIdx.x;
    if (tid == 0) { g_dsum = 0.0; g_dssq = 0.0; }

    for (int i = tid; i < 144; i += 256) {
        int o = i / 9, k = i % 9;
        float sc = g1[o] / sqrtf(rv1[o] + 1e-5f);
        float s = 0.f;
        #pragma unroll
        for (int t = 0; t < TT; t++) s += w1[(o * TT + t) * 9 + k];
        g_w1f[i] = sc * s;
    }
    if (tid < 16) {
        float sc1 = g1[tid] / sqrtf(rv1[tid] + 1e-5f);
        g_s1[tid] = b1[tid] - rm1[tid] * sc1;
        float sc2 = g2[tid] / sqrtf(rv2[tid] + 1e-5f);
        g_s2[tid] = b2[tid] - rm2[tid] * sc2;
        float sc3 = g3[tid] / sqrtf(rv3[tid] + 1e-5f);
        g_s3[tid] = b3[tid] - rm3[tid] * sc3;
    }
    for (int i = tid; i < 1152; i += 256) {
        int t = i & 31, r = (i >> 5) & 1, g = (i >> 6) & 1, tap = i >> 7;
        int co = (g << 3) + (t >> 2);
        int k0 = (t & 3) * 2 + (r << 3);
        float sc2 = g2[co] / sqrtf(rv2[co] + 1e-5f);
        g_wF2[i] = pack_h2(sc2 * w2[((co * 16 + k0) * 9) + tap],
                           sc2 * w2[((co * 16 + k0 + 1) * 9) + tap]);
        float sc3 = g3[co] / sqrtf(rv3[co] + 1e-5f);
        g_wF3[i] = pack_h2(sc3 * w3[((co * 16 + k0) * 9) + tap],
                           sc3 * w3[((co * 16 + k0 + 1) * 9) + tap]);
    }
    for (int i = tid; i < 384; i += 256) {
        int t = i & 31, r = (i >> 5) & 1, n = i >> 6;
        int co = (n << 3) + (t >> 2);
        int k0 = (t & 3) * 2 + (r << 3);
        float v0 = (co < 45) ? w4[co * 16 + k0]     : 0.f;
        float v1 = (co < 45) ? w4[co * 16 + k0 + 1] : 0.f;
        g_wF4[i] = pack_h2(v0, v1);
    }
}

// ---------------- acc = sum|raw_diff| + mean/var reduction ----------------
__global__ void accum_kernel(const float* __restrict__ rd)
{
    int i = blockIdx.x * 256 + threadIdx.x;
    int b = i >> 16;
    int r = i & 65535;
    const float4* p = (const float4*)rd;
    float4 a = make_float4(0.f, 0.f, 0.f, 0.f);
    #pragma unroll
    for (int t = 0; t < TT - 1; t++) {
        float4 v = p[((size_t)(b * (TT - 1) + t)) * 65536 + r];
        a.x += fabsf(v.x); a.y += fabsf(v.y); a.z += fabsf(v.z); a.w += fabsf(v.w);
    }
    ((float4*)g_acc)[i] = a;

    double ls  = (double)a.x + (double)a.y + (double)a.z + (double)a.w;
    double lss = (double)a.x * a.x + (double)a.y * a.y + (double)a.z * a.z + (double)a.w * a.w;
    #pragma unroll
    for (int o = 16; o > 0; o >>= 1) {
        ls  += __shfl_down_sync(0xffffffffu, ls,  o);
        lss += __shfl_down_sync(0xffffffffu, lss, o);
    }
    __shared__ double ss[8], sq[8];
    int wid = threadIdx.x >> 5, lane = threadIdx.x & 31;
    if (lane == 0) { ss[wid] = ls; sq[wid] = lss; }
    __syncthreads();
    if (threadIdx.x == 0) {
        double s = 0.0, q = 0.0;
        #pragma unroll
        for (int w = 0; w < 8; w++) { s += ss[w]; q += sq[w]; }
        atomicAdd(&g_dsum, s);
        atomicAdd(&g_dssq, q);
    }
}

__global__ void finalize_kernel()
{
    double n = (double)NPIX;
    double mean = g_dsum / n;
    double var = (g_dssq - g_dsum * g_dsum / n) / (n - 1.0);
    double sd = sqrt(var);
    g_mean = (float)mean;
    g_inv = (float)(1.0 / (sd + 1e-6));
}

// ---------------- conv1: 1->16 chan, 3x3 d1, fp16 NHWC output ----------------
__global__ void conv1_kernel()
{
    __shared__ float sw[144], sb[16];
    int tid = threadIdx.x;
    if (tid < 144) sw[tid] = g_w1f[tid];
    if (tid < 16)  sb[tid] = g_s1[tid];
    __syncthreads();

    int p = blockIdx.x * 256 + tid;
    int b = p >> 18;
    int rem = p & (HW - 1);
    int y = rem >> 9, x = rem & 511;
    float mean = g_mean, inv = g_inv;

    float m[9];
    #pragma unroll
    for (int ky = 0; ky < 3; ky++) {
        #pragma unroll
        for (int kx = 0; kx < 3; kx++) {
            int yy = y + ky - 1, xx = x + kx - 1;
            bool ok = (yy >= 0) & (yy < HH) & (xx >= 0) & (xx < WW);
            m[ky * 3 + kx] = ok ? (g_acc[(b << 18) + (yy << 9) + xx] - mean) * inv : 0.f;
        }
    }
    float v[16];
    #pragma unroll
    for (int o = 0; o < 16; o++) {
        float s = sb[o];
        #pragma unroll
        for (int k = 0; k < 9; k++) s = fmaf(sw[o * 9 + k], m[k], s);
        v[o] = fmaxf(s, 0.f);
    }
    uint4* out = (uint4*)(g_h1 + (size_t)p * 16);
    out[0] = make_uint4(pack_h2(v[0], v[1]),  pack_h2(v[2], v[3]),
                        pack_h2(v[4], v[5]),  pack_h2(v[6], v[7]));
    out[1] = make_uint4(pack_h2(v[8], v[9]),  pack_h2(v[10], v[11]),
                        pack_h2(v[12], v[13]), pack_h2(v[14], v[15]));
}

// ---------------- conv2/conv3 via ldmatrix + mma.sync (fp16 in, fp32 acc) ----------------
// RING = 2D+PD+2: write slot (i-1 mod RING) never aliases read slots {i,i+D,i+2D}
// nor in-flight groups -> only ONE barrier per row.
template<int DIL>
__global__ __launch_bounds__(256) void conv16_hmma_kernel()
{
    constexpr int XW = 128, YR = 64, PD = 2;
    constexpr int RING = 2 * DIL + PD + 2;       // 8 (D=2) / 12 (D=4)
    constexpr int SEGPX = XW + 2 * DIL;
    constexpr int SLOTB = SEGPX * 48;

    const __half* __restrict__ in  = (DIL == 2) ? g_h1 : g_h2;
    __half*       __restrict__ out = (DIL == 2) ? g_h2 : g_h1;
    const uint32_t* __restrict__ wF = (DIL == 2) ? g_wF2 : g_wF3;
    const float* __restrict__ sB   = (DIL == 2) ? g_s2  : g_s3;

    extern __shared__ char smem[];
    uint32_t sbase = s2u(smem);
    int tid = threadIdx.x;
    int warp = tid >> 5, lane = tid & 31;
    int x0 = blockIdx.x * XW;
    int y0 = blockIdx.y * YR;
    int b  = blockIdx.z;
    const __half* gin = in + (((size_t)b) << 18) * 16;

    uint32_t bw[9][2][2];
    #pragma unroll
    for (int tap = 0; tap < 9; tap++)
        #pragma unroll
        for (int g = 0; g < 2; g++)
            #pragma unroll
            for (int r = 0; r < 2; r++)
                bw[tap][g][r] = wF[(((tap << 1) + g) << 1 | r) * 32 + lane];

    float bc0[2], bc1[2];
    #pragma unroll
    for (int g = 0; g < 2; g++) {
        int c = (g << 3) + ((lane & 3) << 1);
        bc0[g] = sB[c]; bc1[g] = sB[c + 1];
    }

    int prow = warp * 16 + (lane & 7) + ((lane >> 3) & 1) * 8;
    int sel16 = ((lane >> 4) & 1) * 16;

    // idx is the pipeline row index: input row r = y0 - DIL + idx, slot = idx % RING
    auto load_row = [&](int idx) {
        if (idx <= YR - 1 + 2 * DIL) {
            int r = y0 - DIL + idx;
            uint32_t dbase = sbase + (idx % RING) * SLOTB;
            bool rok = (r >= 0) & (r < HH);
            const __half* grow = gin + (((size_t)r) << 9) * 16;
            for (int c = tid; c < SEGPX * 2; c += 256) {
                int s = c >> 1, part = c & 1;
                int x = x0 - DIL + s;
                uint32_t dst = dbase + s * 48 + part * 16;
                if (rok && (unsigned)x < (unsigned)WW)
                    cpasync16(dst, grow + x * 16 + part * 8);
                else
                    sts_zero16(dst);
            }
        }
        cp_commit();
    };

    for (int idx = 0; idx <= 2 * DIL + PD; idx++) load_row(idx);

    for (int i = 0; i < YR; i++) {
        cp_wait<PD>();
        __syncthreads();                           // publishes rows <= i+2D

        load_row(i + 2 * DIL + PD + 1);            // -> slot (i-1)%RING, disjoint from reads

        float d[2][4];
        #pragma unroll
        for (int g = 0; g < 2; g++)
            #pragma unroll
            for (int r = 0; r < 4; r++) d[g][r] = 0.f;

        #pragma unroll
        for (int ky = 0; ky < 3; ky++) {
            uint32_t abase = sbase + ((i + ky * DIL) % RING) * SLOTB;
            #pragma unroll
            for (int kx = 0; kx < 3; kx++) {
                uint32_t a0, a1, a2, a3;
                ldmatrix_x4(a0, a1, a2, a3, abase + (prow + kx * DIL) * 48 + sel16);
                int tap = ky * 3 + kx;
                mma_f16(d[0], a0, a1, a2, a3, bw[tap][0][0], bw[tap][0][1]);
                mma_f16(d[1], a0, a1, a2, a3, bw[tap][1][0], bw[tap][1][1]);
            }
        }

        __half* orow = out + ((((size_t)b << 18) + ((size_t)(y0 + i) << 9) + x0 + warp * 16)) * 16;
        int px = (lane >> 2);
        #pragma unroll
        for (int g = 0; g < 2; g++) {
            int c = (g << 3) + ((lane & 3) << 1);
            uint32_t lo = pack_h2(fmaxf(d[g][0] + bc0[g], 0.f), fmaxf(d[g][1] + bc1[g], 0.f));
            uint32_t hi = pack_h2(fmaxf(d[g][2] + bc0[g], 0.f), fmaxf(d[g][3] + bc1[g], 0.f));
            *(uint32_t*)(orow + px * 16 + c)       = lo;
            *(uint32_t*)(orow + (px + 8) * 16 + c) = hi;
        }
    }
}

// ---------------- final: conv4 1x1 via HMMA + sigmoid + dynamic 3x3 filtering ----------------
// 256 threads = 8 warps; each warp: 16 contiguous pixels of one row. (R7 version)
__global__ __launch_bounds__(256) void final_mma_kernel(
    const float* __restrict__ x, const float* __restrict__ biasp,
    float* __restrict__ out)
{
    __shared__ float sker[8][16][52];   // [warp][px][48 co + pad]

    int tid = threadIdx.x;
    int warp = tid >> 5, lane = tid & 31;
    int pbase = blockIdx.x * 128 + warp * 16;
    int b = pbase >> 18;
    int rem = pbase & (HW - 1);
    int y = rem >> 9, xb0 = rem & 511;

    uint32_t bw[6][2];
    #pragma unroll
    for (int n = 0; n < 6; n++) {
        bw[n][0] = g_wF4[(n * 2 + 0) * 32 + lane];
        bw[n][1] = g_wF4[(n * 2 + 1) * 32 + lane];
    }

    const __half* hb = g_h1 + (size_t)pbase * 16;
    int arow = lane >> 2;
    int cc = (lane & 3) * 2;
    uint32_t a0 = *(const uint32_t*)(hb + arow * 16 + cc);
    uint32_t a1 = *(const uint32_t*)(hb + (arow + 8) * 16 + cc);
    uint32_t a2 = *(const uint32_t*)(hb + arow * 16 + cc + 8);
    uint32_t a3 = *(const uint32_t*)(hb + (arow + 8) * 16 + cc + 8);

    float d[6][4];
    #pragma unroll
    for (int n = 0; n < 6; n++)
        #pragma unroll
        for (int r = 0; r < 4; r++) d[n][r] = 0.f;
    #pragma unroll
    for (int n = 0; n < 6; n++)
        mma_f16(d[n], a0, a1, a2, a3, bw[n][0], bw[n][1]);

    float bias = biasp[0];
    #pragma unroll
    for (int n = 0; n < 6; n++) {
        int col = n * 8 + cc;
        #pragma unroll
        for (int half = 0; half < 2; half++) {
            int px = arow + half * 8;
            float z0 = d[n][half * 2 + 0] + bias;
            float z1 = d[n][half * 2 + 1] + bias;
            float k0 = fmaf(10.f, 1.f / (1.f + __expf(-z0)), 0.1f);
            float k1 = fmaf(10.f, 1.f / (1.f + __expf(-z1)), 0.1f);
            sker[warp][px][col]     = k0;
            sker[warp][px][col + 1] = k1;
        }
    }
    __syncwarp();

    int px = lane & 15;
    int grp = lane >> 4;
    int gx = xb0 + px;
    const float* kp = sker[warp][px];
    int tlo = grp ? 3 : 0;
    int thi = grp ? 5 : 3;
    for (int t = tlo; t < thi; t++) {
        const float* xp = x + ((size_t)(b * TT + t) << 18);
        float o = 0.f;
        #pragma unroll
        for (int dy = 0; dy < 3; dy++) {
            int yy = y + dy - 1;
            bool yok = (yy >= 0) & (yy < HH);
            #pragma unroll
            for (int dx = 0; dx < 3; dx++) {
                int xx = gx + dx - 1;
                bool ok = yok & (xx >= 0) & (xx < WW);
                float xv = ok ? xp[(yy << 9) + xx] : 0.f;
                o = fmaf(kp[t * 9 + dy * 3 + dx], xv, o);
            }
        }
        out[((size_t)(b * TT + t) << 18) + (y << 9) + gx] = o;
    }
}

// ---------------- launch ----------------
extern "C" void kernel_launch(void* const* d_in, const int* in_sizes, int n_in,
                              void* d_out, int out_size)
{
    const float* x_aligned = (const float*)d_in[0];
    const float* raw_diff  = (const float*)d_in[1];
    const float* w1  = (const float*)d_in[2];
    const float* g1  = (const float*)d_in[3];
    const float* b1  = (const float*)d_in[4];
    const float* rm1 = (const float*)d_in[5];
    const float* rv1 = (const float*)d_in[6];
    const float* w2  = (const float*)d_in[7];
    const float* g2  = (const float*)d_in[8];
    const float* b2  = (const float*)d_in[9];
    const float* rm2 = (const float*)d_in[10];
    const float* rv2 = (const float*)d_in[11];
    const float* w3  = (const float*)d_in[12];
    const float* g3  = (const float*)d_in[13];
    const float* b3  = (const float*)d_in[14];
    const float* rm3 = (const float*)d_in[15];
    const float* rv3 = (const float*)d_in[16];
    const float* w4  = (const float*)d_in[17];
    const float* bias = (const float*)d_in[18];
    float* out = (float*)d_out;

    const int SMEM2 = 8  * (132 * 48);   // 50,688 B
    const int SMEM4 = 12 * (136 * 48);   // 78,336 B
    static bool attr_done = false;
    if (!attr_done) {
        cudaFuncSetAttribute(conv16_hmma_kernel<2>, cudaFuncAttributeMaxDynamicSharedMemorySize, SMEM2);
        cudaFuncSetAttribute(conv16_hmma_kernel<4>, cudaFuncAttributeMaxDynamicSharedMemorySize, SMEM4);
        attr_done = true;
    }

    prep_kernel<<<1, 256>>>(w1, g1, b1, rm1, rv1, w2, g2, b2, rm2, rv2,
                            w3, g3, b3, rm3, rv3, w4);
    accum_kernel<<<NPIX / 4 / 256, 256>>>(raw_diff);
    finalize_kernel<<<1, 1>>>();
    conv1_kernel<<<NPIX / 256, 256>>>();
    {
        dim3 grd(WW / 128, HH / 64, BB);   // (4, 8, 8)
        conv16_hmma_kernel<2><<<grd, 256, SMEM2>>>();
        conv16_hmma_kernel<4><<<grd, 256, SMEM4>>>();
    }
    final_mma_kernel<<<NPIX / 128, 256>>>(x_aligned, bias, out);
}

// round 13
// speedup vs baseline: 1.2998x; 1.0598x over previous
#include <cuda_runtime.h>
#include <cuda_fp16.h>
#include <math.h>
#include <stdint.h>

#define BB 8
#define TT 5
#define HH 512
#define WW 512
#define HW (HH*WW)
#define MID 16
#define NPIX (BB*HW)

// ---------------- scratch (no allocation allowed) ----------------
__device__ float  g_acc[NPIX];                    // 8 MB
__device__ __half g_h1[(size_t)NPIX*MID];         // 67 MB (conv1 out / conv2 in)
__device__ __half g_h2[(size_t)NPIX*MID];         // 67 MB (conv2 out / conv3 in)
__device__ double g_dsum, g_dssq;
__device__ float g_mean, g_inv;
__device__ float g_w1f[144], g_s1[16];
__device__ uint32_t g_wF2[1152];                  // B fragments (half2) conv2
__device__ uint32_t g_wF3[1152];                  // B fragments (half2) conv3
__device__ uint32_t g_wF4[384];                   // B fragments (half2) conv4 1x1 (48-co pad)
__device__ float g_s2[16], g_s3[16];

// ---------------- PTX helpers ----------------
__device__ __forceinline__ uint32_t s2u(const void* p) {
    uint32_t a;
    asm("{ .reg .u64 t; cvta.to.shared.u64 t, %1; cvt.u32.u64 %0, t; }" : "=r"(a) : "l"(p));
    return a;
}
__device__ __forceinline__ void cpasync16(uint32_t dst, const void* src) {
    asm volatile("cp.async.cg.shared.global [%0], [%1], 16;" :: "r"(dst), "l"(src));
}
__device__ __forceinline__ void cp_commit() {
    asm volatile("cp.async.commit_group;" ::: "memory");
}
template<int N> __device__ __forceinline__ void cp_wait() {
    asm volatile("cp.async.wait_group %0;" :: "n"(N) : "memory");
}
__device__ __forceinline__ void sts_zero16(uint32_t dst) {
    asm volatile("st.shared.v4.u32 [%0], {%1,%1,%1,%1};" :: "r"(dst), "r"(0u) : "memory");
}
__device__ __forceinline__ void ldmatrix_x4(uint32_t& r0, uint32_t& r1, uint32_t& r2,
                                            uint32_t& r3, uint32_t addr) {
    asm volatile("ldmatrix.sync.aligned.m8n8.x4.shared.b16 {%0,%1,%2,%3}, [%4];"
                 : "=r"(r0), "=r"(r1), "=r"(r2), "=r"(r3) : "r"(addr));
}
__device__ __forceinline__ void mma_f16(float* d, uint32_t a0, uint32_t a1, uint32_t a2,
                                        uint32_t a3, uint32_t b0, uint32_t b1) {
    asm volatile(
        "mma.sync.aligned.m16n8k16.row.col.f32.f16.f16.f32 "
        "{%0,%1,%2,%3}, {%4,%5,%6,%7}, {%8,%9}, {%0,%1,%2,%3};"
        : "+f"(d[0]), "+f"(d[1]), "+f"(d[2]), "+f"(d[3])
        : "r"(a0), "r"(a1), "r"(a2), "r"(a3), "r"(b0), "r"(b1));
}
__device__ __forceinline__ uint32_t pack_h2(float a, float b) {
    __half2 h = __floats2half2_rn(a, b);
    return *reinterpret_cast<uint32_t*>(&h);
}

// ---------------- prep: fold BN into conv weights, build B fragments ----------------
__global__ void prep_kernel(
    const float* __restrict__ w1, const float* __restrict__ g1, const float* __restrict__ b1,
    const float* __restrict__ rm1, const float* __restrict__ rv1,
    const float* __restrict__ w2, const float* __restrict__ g2, const float* __restrict__ b2,
    const float* __restrict__ rm2, const float* __restrict__ rv2,
    const float* __restrict__ w3, const float* __restrict__ g3, const float* __restrict__ b3,
    const float* __restrict__ rm3, const float* __restrict__ rv3,
    const float* __restrict__ w4)
{
    int tid = threadIdx.x;
    if (tid == 0) { g_dsum = 0.0; g_dssq = 0.0; }

    for (int i = tid; i < 144; i += 256) {
        int o = i / 9, k = i % 9;
        float sc = g1[o] / sqrtf(rv1[o] + 1e-5f);
        float s = 0.f;
        #pragma unroll
        for (int t = 0; t < TT; t++) s += w1[(o * TT + t) * 9 + k];
        g_w1f[i] = sc * s;
    }
    if (tid < 16) {
        float sc1 = g1[tid] / sqrtf(rv1[tid] + 1e-5f);
        g_s1[tid] = b1[tid] - rm1[tid] * sc1;
        float sc2 = g2[tid] / sqrtf(rv2[tid] + 1e-5f);
        g_s2[tid] = b2[tid] - rm2[tid] * sc2;
        float sc3 = g3[tid] / sqrtf(rv3[tid] + 1e-5f);
        g_s3[tid] = b3[tid] - rm3[tid] * sc3;
    }
    for (int i = tid; i < 1152; i += 256) {
        int t = i & 31, r = (i >> 5) & 1, g = (i >> 6) & 1, tap = i >> 7;
        int co = (g << 3) + (t >> 2);
        int k0 = (t & 3) * 2 + (r << 3);
        float sc2 = g2[co] / sqrtf(rv2[co] + 1e-5f);
        g_wF2[i] = pack_h2(sc2 * w2[((co * 16 + k0) * 9) + tap],
                           sc2 * w2[((co * 16 + k0 + 1) * 9) + tap]);
        float sc3 = g3[co] / sqrtf(rv3[co] + 1e-5f);
        g_wF3[i] = pack_h2(sc3 * w3[((co * 16 + k0) * 9) + tap],
                           sc3 * w3[((co * 16 + k0 + 1) * 9) + tap]);
    }
    for (int i = tid; i < 384; i += 256) {
        int t = i & 31, r = (i >> 5) & 1, n = i >> 6;
        int co = (n << 3) + (t >> 2);
        int k0 = (t & 3) * 2 + (r << 3);
        float v0 = (co < 45) ? w4[co * 16 + k0]     : 0.f;
        float v1 = (co < 45) ? w4[co * 16 + k0 + 1] : 0.f;
        g_wF4[i] = pack_h2(v0, v1);
    }
}

// ---------------- acc = sum|raw_diff| + mean/var reduction ----------------
__global__ void accum_kernel(const float* __restrict__ rd)
{
    int i = blockIdx.x * 256 + threadIdx.x;
    int b = i >> 16;
    int r = i & 65535;
    const float4* p = (const float4*)rd;
    float4 a = make_float4(0.f, 0.f, 0.f, 0.f);
    #pragma unroll
    for (int t = 0; t < TT - 1; t++) {
        float4 v = p[((size_t)(b * (TT - 1) + t)) * 65536 + r];
        a.x += fabsf(v.x); a.y += fabsf(v.y); a.z += fabsf(v.z); a.w += fabsf(v.w);
    }
    ((float4*)g_acc)[i] = a;

    double ls  = (double)a.x + (double)a.y + (double)a.z + (double)a.w;
    double lss = (double)a.x * a.x + (double)a.y * a.y + (double)a.z * a.z + (double)a.w * a.w;
    #pragma unroll
    for (int o = 16; o > 0; o >>= 1) {
        ls  += __shfl_down_sync(0xffffffffu, ls,  o);
        lss += __shfl_down_sync(0xffffffffu, lss, o);
    }
    __shared__ double ss[8], sq[8];
    int wid = threadIdx.x >> 5, lane = threadIdx.x & 31;
    if (lane == 0) { ss[wid] = ls; sq[wid] = lss; }
    __syncthreads();
    if (threadIdx.x == 0) {
        double s = 0.0, q = 0.0;
        #pragma unroll
        for (int w = 0; w < 8; w++) { s += ss[w]; q += sq[w]; }
        atomicAdd(&g_dsum, s);
        atomicAdd(&g_dssq, q);
    }
}

__global__ void finalize_kernel()
{
    double n = (double)NPIX;
    double mean = g_dsum / n;
    double var = (g_dssq - g_dsum * g_dsum / n) / (n - 1.0);
    double sd = sqrt(var);
    g_mean = (float)mean;
    g_inv = (float)(1.0 / (sd + 1e-6));
}

// ---------------- conv1: 1->16 chan, 3x3 d1, fp16 NHWC output ----------------
__global__ void conv1_kernel()
{
    __shared__ float sw[144], sb[16];
    int tid = threadIdx.x;
    if (tid < 144) sw[tid] = g_w1f[tid];
    if (tid < 16)  sb[tid] = g_s1[tid];
    __syncthreads();

    int p = blockIdx.x * 256 + tid;
    int b = p >> 18;
    int rem = p & (HW - 1);
    int y = rem >> 9, x = rem & 511;
    float mean = g_mean, inv = g_inv;

    float m[9];
    #pragma unroll
    for (int ky = 0; ky < 3; ky++) {
        #pragma unroll
        for (int kx = 0; kx < 3; kx++) {
            int yy = y + ky - 1, xx = x + kx - 1;
            bool ok = (yy >= 0) & (yy < HH) & (xx >= 0) & (xx < WW);
            m[ky * 3 + kx] = ok ? (g_acc[(b << 18) + (yy << 9) + xx] - mean) * inv : 0.f;
        }
    }
    float v[16];
    #pragma unroll
    for (int o = 0; o < 16; o++) {
        float s = sb[o];
        #pragma unroll
        for (int k = 0; k < 9; k++) s = fmaf(sw[o * 9 + k], m[k], s);
        v[o] = fmaxf(s, 0.f);
    }
    uint4* out = (uint4*)(g_h1 + (size_t)p * 16);
    out[0] = make_uint4(pack_h2(v[0], v[1]),  pack_h2(v[2], v[3]),
                        pack_h2(v[4], v[5]),  pack_h2(v[6], v[7]));
    out[1] = make_uint4(pack_h2(v[8], v[9]),  pack_h2(v[10], v[11]),
                        pack_h2(v[12], v[13]), pack_h2(v[14], v[15]));
}

// ---------------- conv2 via ldmatrix + mma.sync (g_h1 -> g_h2), single barrier/row ----
__global__ __launch_bounds__(256) void conv2_hmma_kernel()
{
    constexpr int DIL = 2, XW = 128, YR = 64, PD = 2;
    constexpr int RING = 2 * DIL + PD + 2;       // 8
    constexpr int SEGPX = XW + 2 * DIL;
    constexpr int SLOTB = SEGPX * 48;

    const __half* __restrict__ in  = g_h1;
    __half*       __restrict__ out = g_h2;

    extern __shared__ char smem[];
    uint32_t sbase = s2u(smem);
    int tid = threadIdx.x;
    int warp = tid >> 5, lane = tid & 31;
    int x0 = blockIdx.x * XW;
    int y0 = blockIdx.y * YR;
    int b  = blockIdx.z;
    const __half* gin = in + (((size_t)b) << 18) * 16;

    uint32_t bw[9][2][2];
    #pragma unroll
    for (int tap = 0; tap < 9; tap++)
        #pragma unroll
        for (int g = 0; g < 2; g++)
            #pragma unroll
            for (int r = 0; r < 2; r++)
                bw[tap][g][r] = g_wF2[(((tap << 1) + g) << 1 | r) * 32 + lane];

    float bc0[2], bc1[2];
    #pragma unroll
    for (int g = 0; g < 2; g++) {
        int c = (g << 3) + ((lane & 3) << 1);
        bc0[g] = g_s2[c]; bc1[g] = g_s2[c + 1];
    }

    int prow = warp * 16 + (lane & 7) + ((lane >> 3) & 1) * 8;
    int sel16 = ((lane >> 4) & 1) * 16;

    auto load_row = [&](int idx) {
        if (idx <= YR - 1 + 2 * DIL) {
            int r = y0 - DIL + idx;
            uint32_t dbase = sbase + (idx % RING) * SLOTB;
            bool rok = (r >= 0) & (r < HH);
            const __half* grow = gin + (((size_t)r) << 9) * 16;
            for (int c = tid; c < SEGPX * 2; c += 256) {
                int s = c >> 1, part = c & 1;
                int x = x0 - DIL + s;
                uint32_t dst = dbase + s * 48 + part * 16;
                if (rok && (unsigned)x < (unsigned)WW)
                    cpasync16(dst, grow + x * 16 + part * 8);
                else
                    sts_zero16(dst);
            }
        }
        cp_commit();
    };

    for (int idx = 0; idx <= 2 * DIL + PD; idx++) load_row(idx);

    for (int i = 0; i < YR; i++) {
        cp_wait<PD>();
        __syncthreads();

        load_row(i + 2 * DIL + PD + 1);

        float d[2][4];
        #pragma unroll
        for (int g = 0; g < 2; g++)
            #pragma unroll
            for (int r = 0; r < 4; r++) d[g][r] = 0.f;

        #pragma unroll
        for (int ky = 0; ky < 3; ky++) {
            uint32_t abase = sbase + ((i + ky * DIL) % RING) * SLOTB;
            #pragma unroll
            for (int kx = 0; kx < 3; kx++) {
                uint32_t a0, a1, a2, a3;
                ldmatrix_x4(a0, a1, a2, a3, abase + (prow + kx * DIL) * 48 + sel16);
                int tap = ky * 3 + kx;
                mma_f16(d[0], a0, a1, a2, a3, bw[tap][0][0], bw[tap][0][1]);
                mma_f16(d[1], a0, a1, a2, a3, bw[tap][1][0], bw[tap][1][1]);
            }
        }

        __half* orow = out + ((((size_t)b << 18) + ((size_t)(y0 + i) << 9) + x0 + warp * 16)) * 16;
        int px = (lane >> 2);
        #pragma unroll
        for (int g = 0; g < 2; g++) {
            int c = (g << 3) + ((lane & 3) << 1);
            uint32_t lo = pack_h2(fmaxf(d[g][0] + bc0[g], 0.f), fmaxf(d[g][1] + bc1[g], 0.f));
            uint32_t hi = pack_h2(fmaxf(d[g][2] + bc0[g], 0.f), fmaxf(d[g][3] + bc1[g], 0.f));
            *(uint32_t*)(orow + px * 16 + c)       = lo;
            *(uint32_t*)(orow + (px + 8) * 16 + c) = hi;
        }
    }
}

// ---------------- fused conv3 + conv4(1x1) + sigmoid + dynamic filtering ----------------
// g_h2 -> (conv3 HMMA, D frags == conv4 A frags) -> conv4 HMMA -> sigmoid -> sker
// -> per-warp dynamic 3x3 filtering of x_aligned -> out. h1 never touches DRAM.
__global__ __launch_bounds__(256) void conv3_final_kernel(
    const float* __restrict__ x, const float* __restrict__ biasp,
    float* __restrict__ out)
{
    constexpr int DIL = 4, XW = 128, YR = 64, PD = 2;
    constexpr int RING = 2 * DIL + PD + 2;       // 12
    constexpr int SEGPX = XW + 2 * DIL;          // 136
    constexpr int SLOTB = SEGPX * 48;            // 6528

    extern __shared__ char smem[];
    uint32_t sbase = s2u(smem);
    float (*sker)[16][52] = (float (*)[16][52])(smem + RING * SLOTB);

    int tid = threadIdx.x;
    int warp = tid >> 5, lane = tid & 31;
    int x0 = blockIdx.x * XW;
    int y0 = blockIdx.y * YR;
    int b  = blockIdx.z;
    const __half* gin = g_h2 + (((size_t)b) << 18) * 16;

    // conv3 B fragments + bias
    uint32_t bw[9][2][2];
    #pragma unroll
    for (int tap = 0; tap < 9; tap++)
        #pragma unroll
        for (int g = 0; g < 2; g++)
            #pragma unroll
            for (int r = 0; r < 2; r++)
                bw[tap][g][r] = g_wF3[(((tap << 1) + g) << 1 | r) * 32 + lane];
    float bc0[2], bc1[2];
    #pragma unroll
    for (int g = 0; g < 2; g++) {
        int c = (g << 3) + ((lane & 3) << 1);
        bc0[g] = g_s3[c]; bc1[g] = g_s3[c + 1];
    }
    // conv4 B fragments
    uint32_t bw4[6][2];
    #pragma unroll
    for (int n = 0; n < 6; n++) {
        bw4[n][0] = g_wF4[(n * 2 + 0) * 32 + lane];
        bw4[n][1] = g_wF4[(n * 2 + 1) * 32 + lane];
    }
    float bias = biasp[0];

    int prow = warp * 16 + (lane & 7) + ((lane >> 3) & 1) * 8;
    int sel16 = ((lane >> 4) & 1) * 16;
    int arow = lane >> 2;
    int cc = (lane & 3) * 2;

    auto load_row = [&](int idx) {
        if (idx <= YR - 1 + 2 * DIL) {
            int r = y0 - DIL + idx;
            uint32_t dbase = sbase + (idx % RING) * SLOTB;
            bool rok = (r >= 0) & (r < HH);
            const __half* grow = gin + (((size_t)r) << 9) * 16;
            for (int c = tid; c < SEGPX * 2; c += 256) {
                int s = c >> 1, part = c & 1;
                int xx = x0 - DIL + s;
                uint32_t dst = dbase + s * 48 + part * 16;
                if (rok && (unsigned)xx < (unsigned)WW)
                    cpasync16(dst, grow + xx * 16 + part * 8);
                else
                    sts_zero16(dst);
            }
        }
        cp_commit();
    };

    for (int idx = 0; idx <= 2 * DIL + PD; idx++) load_row(idx);

    for (int i = 0; i < YR; i++) {
        cp_wait<PD>();
        __syncthreads();

        load_row(i + 2 * DIL + PD + 1);

        // --- conv3 MMAs ---
        float d[2][4];
        #pragma unroll
        for (int g = 0; g < 2; g++)
            #pragma unroll
            for (int r = 0; r < 4; r++) d[g][r] = 0.f;
        #pragma unroll
        for (int ky = 0; ky < 3; ky++) {
            uint32_t abase = sbase + ((i + ky * DIL) % RING) * SLOTB;
            #pragma unroll
            for (int kx = 0; kx < 3; kx++) {
                uint32_t a0, a1, a2, a3;
                ldmatrix_x4(a0, a1, a2, a3, abase + (prow + kx * DIL) * 48 + sel16);
                int tap = ky * 3 + kx;
                mma_f16(d[0], a0, a1, a2, a3, bw[tap][0][0], bw[tap][0][1]);
                mma_f16(d[1], a0, a1, a2, a3, bw[tap][1][0], bw[tap][1][1]);
            }
        }

        // --- bias+ReLU+fp16 pack: conv3 D frags -> conv4 A frags (identity layout) ---
        uint32_t a0 = pack_h2(fmaxf(d[0][0] + bc0[0], 0.f), fmaxf(d[0][1] + bc1[0], 0.f));
        uint32_t a1 = pack_h2(fmaxf(d[0][2] + bc0[0], 0.f), fmaxf(d[0][3] + bc1[0], 0.f));
        uint32_t a2 = pack_h2(fmaxf(d[1][0] + bc0[1], 0.f), fmaxf(d[1][1] + bc1[1], 0.f));
        uint32_t a3 = pack_h2(fmaxf(d[1][2] + bc0[1], 0.f), fmaxf(d[1][3] + bc1[1], 0.f));

        // --- conv4 1x1 MMAs ---
        float d4[6][4];
        #pragma unroll
        for (int n = 0; n < 6; n++)
            #pragma unroll
            for (int r = 0; r < 4; r++) d4[n][r] = 0.f;
        #pragma unroll
        for (int n = 0; n < 6; n++)
            mma_f16(d4[n], a0, a1, a2, a3, bw4[n][0], bw4[n][1]);

        // --- sigmoid -> per-warp sker tile ---
        #pragma unroll
        for (int n = 0; n < 6; n++) {
            int col = n * 8 + cc;
            #pragma unroll
            for (int half = 0; half < 2; half++) {
                int px = arow + half * 8;
                float z0 = d4[n][half * 2 + 0] + bias;
                float z1 = d4[n][half * 2 + 1] + bias;
                float k0 = fmaf(10.f, 1.f / (1.f + __expf(-z0)), 0.1f);
                float k1 = fmaf(10.f, 1.f / (1.f + __expf(-z1)), 0.1f);
                sker[warp][px][col]     = k0;
                sker[warp][px][col + 1] = k1;
            }
        }
        __syncwarp();

        // --- dynamic filtering: lanes 0-15 -> t=0..2, 16-31 -> t=3,4 ---
        int y = y0 + i;
        int px = lane & 15;
        int grp = lane >> 4;
        int gx = x0 + warp * 16 + px;
        const float* kp = sker[warp][px];
        int tlo = grp ? 3 : 0;
        int thi = grp ? 5 : 3;
        for (int t = tlo; t < thi; t++) {
            const float* xp = x + ((size_t)(b * TT + t) << 18);
            float o = 0.f;
            #pragma unroll
            for (int dy = 0; dy < 3; dy++) {
                int yy = y + dy - 1;
                bool yok = (yy >= 0) & (yy < HH);
                #pragma unroll
                for (int dx = 0; dx < 3; dx++) {
                    int xx = gx + dx - 1;
                    bool ok = yok & (xx >= 0) & (xx < WW);
                    float xv = ok ? xp[(yy << 9) + xx] : 0.f;
                    o = fmaf(kp[t * 9 + dy * 3 + dx], xv, o);
                }
            }
            out[((size_t)(b * TT + t) << 18) + (y << 9) + gx] = o;
        }
        __syncwarp();      // sker reads done before next row's overwrite
    }
}

// ---------------- launch ----------------
extern "C" void kernel_launch(void* const* d_in, const int* in_sizes, int n_in,
                              void* d_out, int out_size)
{
    const float* x_aligned = (const float*)d_in[0];
    const float* raw_diff  = (const float*)d_in[1];
    const float* w1  = (const float*)d_in[2];
    const float* g1  = (const float*)d_in[3];
    const float* b1  = (const float*)d_in[4];
    const float* rm1 = (const float*)d_in[5];
    const float* rv1 = (const float*)d_in[6];
    const float* w2  = (const float*)d_in[7];
    const float* g2  = (const float*)d_in[8];
    const float* b2  = (const float*)d_in[9];
    const float* rm2 = (const float*)d_in[10];
    const float* rv2 = (const float*)d_in[11];
    const float* w3  = (const float*)d_in[12];
    const float* g3  = (const float*)d_in[13];
    const float* b3  = (const float*)d_in[14];
    const float* rm3 = (const float*)d_in[15];
    const float* rv3 = (const float*)d_in[16];
    const float* w4  = (const float*)d_in[17];
    const float* bias = (const float*)d_in[18];
    float* out = (float*)d_out;

    const int SMEM2 = 8 * (132 * 48);                       // 50,688 B
    const int SMEM3 = 12 * (136 * 48) + 8 * 16 * 52 * 4;    // 78,336 + 26,624 = 104,960 B
    static bool attr_done = false;
    if (!attr_done) {
        cudaFuncSetAttribute(conv2_hmma_kernel,  cudaFuncAttributeMaxDynamicSharedMemorySize, SMEM2);
        cudaFuncSetAttribute(conv3_final_kernel, cudaFuncAttributeMaxDynamicSharedMemorySize, SMEM3);
        attr_done = true;
    }

    prep_kernel<<<1, 256>>>(w1, g1, b1, rm1, rv1, w2, g2, b2, rm2, rv2,
                            w3, g3, b3, rm3, rv3, w4);
    accum_kernel<<<NPIX / 4 / 256, 256>>>(raw_diff);
    finalize_kernel<<<1, 1>>>();
    conv1_kernel<<<NPIX / 256, 256>>>();
    {
        dim3 grd(WW / 128, HH / 64, BB);   // (4, 8, 8)
        conv2_hmma_kernel<<<grd, 256, SMEM2>>>();
        conv3_final_kernel<<<grd, 256, SMEM3>>>(x_aligned, bias, out);
    }
}

// round 14
// speedup vs baseline: 1.8695x; 1.4383x over previous
#include <cuda_runtime.h>
#include <cuda_fp16.h>
#include <math.h>
#include <stdint.h>

#define BB 8
#define TT 5
#define HH 512
#define WW 512
#define HW (HH*WW)
#define MID 16
#define NPIX (BB*HW)

// ---------------- scratch (no allocation allowed) ----------------
__device__ float  g_acc[NPIX];                    // 8 MB
__device__ __half g_h1[(size_t)NPIX*MID];         // 67 MB
__device__ __half g_h2[(size_t)NPIX*MID];         // 67 MB
__device__ double g_dsum, g_dssq;
__device__ float g_mean, g_inv;
__device__ float g_w1f[144], g_s1[16];
__device__ uint32_t g_wF2[1152];                  // B fragments (half2) conv2
__device__ uint32_t g_wF3[1152];                  // B fragments (half2) conv3
__device__ uint32_t g_wF4[384];                   // B fragments (half2) conv4 1x1 (48-co pad)
__device__ float g_s2[16], g_s3[16];

// ---------------- PTX helpers ----------------
__device__ __forceinline__ uint32_t s2u(const void* p) {
    uint32_t a;
    asm("{ .reg .u64 t; cvta.to.shared.u64 t, %1; cvt.u32.u64 %0, t; }" : "=r"(a) : "l"(p));
    return a;
}
__device__ __forceinline__ void cpasync16(uint32_t dst, const void* src) {
    asm volatile("cp.async.cg.shared.global [%0], [%1], 16;" :: "r"(dst), "l"(src));
}
__device__ __forceinline__ void cp_commit() {
    asm volatile("cp.async.commit_group;" ::: "memory");
}
template<int N> __device__ __forceinline__ void cp_wait() {
    asm volatile("cp.async.wait_group %0;" :: "n"(N) : "memory");
}
__device__ __forceinline__ void sts_zero16(uint32_t dst) {
    asm volatile("st.shared.v4.u32 [%0], {%1,%1,%1,%1};" :: "r"(dst), "r"(0u) : "memory");
}
__device__ __forceinline__ void ldmatrix_x4(uint32_t& r0, uint32_t& r1, uint32_t& r2,
                                            uint32_t& r3, uint32_t addr) {
    asm volatile("ldmatrix.sync.aligned.m8n8.x4.shared.b16 {%0,%1,%2,%3}, [%4];"
                 : "=r"(r0), "=r"(r1), "=r"(r2), "=r"(r3) : "r"(addr));
}
__device__ __forceinline__ void mma_f16(float* d, uint32_t a0, uint32_t a1, uint32_t a2,
                                        uint32_t a3, uint32_t b0, uint32_t b1) {
    asm volatile(
        "mma.sync.aligned.m16n8k16.row.col.f32.f16.f16.f32 "
        "{%0,%1,%2,%3}, {%4,%5,%6,%7}, {%8,%9}, {%0,%1,%2,%3};"
        : "+f"(d[0]), "+f"(d[1]), "+f"(d[2]), "+f"(d[3])
        : "r"(a0), "r"(a1), "r"(a2), "r"(a3), "r"(b0), "r"(b1));
}
__device__ __forceinline__ uint32_t pack_h2(float a, float b) {
    __half2 h = __floats2half2_rn(a, b);
    return *reinterpret_cast<uint32_t*>(&h);
}

// ---------------- prep: fold BN into conv weights, build B fragments ----------------
__global__ void prep_kernel(
    const float* __restrict__ w1, const float* __restrict__ g1, const float* __restrict__ b1,
    const float* __restrict__ rm1, const float* __restrict__ rv1,
    const float* __restrict__ w2, const float* __restrict__ g2, const float* __restrict__ b2,
    const float* __restrict__ rm2, const float* __restrict__ rv2,
    const float* __restrict__ w3, const float* __restrict__ g3, const float* __restrict__ b3,
    const float* __restrict__ rm3, const float* __restrict__ rv3,
    const float* __restrict__ w4)
{
    int tid = threadIdx.x;
    if (tid == 0) { g_dsum = 0.0; g_dssq = 0.0; }

    for (int i = tid; i < 144; i += 256) {
        int o = i / 9, k = i % 9;
        float sc = g1[o] / sqrtf(rv1[o] + 1e-5f);
        float s = 0.f;
        #pragma unroll
        for (int t = 0; t < TT; t++) s += w1[(o * TT + t) * 9 + k];
        g_w1f[i] = sc * s;
    }
    if (tid < 16) {
        float sc1 = g1[tid] / sqrtf(rv1[tid] + 1e-5f);
        g_s1[tid] = b1[tid] - rm1[tid] * sc1;
        float sc2 = g2[tid] / sqrtf(rv2[tid] + 1e-5f);
        g_s2[tid] = b2[tid] - rm2[tid] * sc2;
        float sc3 = g3[tid] / sqrtf(rv3[tid] + 1e-5f);
        g_s3[tid] = b3[tid] - rm3[tid] * sc3;
    }
    for (int i = tid; i < 1152; i += 256) {
        int t = i & 31, r = (i >> 5) & 1, g = (i >> 6) & 1, tap = i >> 7;
        int co = (g << 3) + (t >> 2);
        int k0 = (t & 3) * 2 + (r << 3);
        float sc2 = g2[co] / sqrtf(rv2[co] + 1e-5f);
        g_wF2[i] = pack_h2(sc2 * w2[((co * 16 + k0) * 9) + tap],
                           sc2 * w2[((co * 16 + k0 + 1) * 9) + tap]);
        float sc3 = g3[co] / sqrtf(rv3[co] + 1e-5f);
        g_wF3[i] = pack_h2(sc3 * w3[((co * 16 + k0) * 9) + tap],
                           sc3 * w3[((co * 16 + k0 + 1) * 9) + tap]);
    }
    for (int i = tid; i < 384; i += 256) {
        int t = i & 31, r = (i >> 5) & 1, n = i >> 6;
        int co = (n << 3) + (t >> 2);
        int k0 = (t & 3) * 2 + (r << 3);
        float v0 = (co < 45) ? w4[co * 16 + k0]     : 0.f;
        float v1 = (co < 45) ? w4[co * 16 + k0 + 1] : 0.f;
        g_wF4[i] = pack_h2(v0, v1);
    }
}

// ---------------- acc = sum|raw_diff| + mean/var reduction ----------------
__global__ void accum_kernel(const float* __restrict__ rd)
{
    int i = blockIdx.x * 256 + threadIdx.x;
    int b = i >> 16;
    int r = i & 65535;
    const float4* p = (const float4*)rd;
    float4 a = make_float4(0.f, 0.f, 0.f, 0.f);
    #pragma unroll
    for (int t = 0; t < TT - 1; t++) {
        float4 v = p[((size_t)(b * (TT - 1) + t)) * 65536 + r];
        a.x += fabsf(v.x); a.y += fabsf(v.y); a.z += fabsf(v.z); a.w += fabsf(v.w);
    }
    ((float4*)g_acc)[i] = a;

    double ls  = (double)a.x + (double)a.y + (double)a.z + (double)a.w;
    double lss = (double)a.x * a.x + (double)a.y * a.y + (double)a.z * a.z + (double)a.w * a.w;
    #pragma unroll
    for (int o = 16; o > 0; o >>= 1) {
        ls  += __shfl_down_sync(0xffffffffu, ls,  o);
        lss += __shfl_down_sync(0xffffffffu, lss, o);
    }
    __shared__ double ss[8], sq[8];
    int wid = threadIdx.x >> 5, lane = threadIdx.x & 31;
    if (lane == 0) { ss[wid] = ls; sq[wid] = lss; }
    __syncthreads();
    if (threadIdx.x == 0) {
        double s = 0.0, q = 0.0;
        #pragma unroll
        for (int w = 0; w < 8; w++) { s += ss[w]; q += sq[w]; }
        atomicAdd(&g_dsum, s);
        atomicAdd(&g_dssq, q);
    }
}

__global__ void finalize_kernel()
{
    double n = (double)NPIX;
    double mean = g_dsum / n;
    double var = (g_dssq - g_dsum * g_dsum / n) / (n - 1.0);
    double sd = sqrt(var);
    g_mean = (float)mean;
    g_inv = (float)(1.0 / (sd + 1e-6));
}

// ---------------- conv1: 1->16 chan, 3x3 d1, fp16 NHWC output ----------------
__global__ void conv1_kernel()
{
    __shared__ float sw[144], sb[16];
    int tid = threadIdx.x;
    if (tid < 144) sw[tid] = g_w1f[tid];
    if (tid < 16)  sb[tid] = g_s1[tid];
    __syncthreads();

    int p = blockIdx.x * 256 + tid;
    int b = p >> 18;
    int rem = p & (HW - 1);
    int y = rem >> 9, x = rem & 511;
    float mean = g_mean, inv = g_inv;

    float m[9];
    #pragma unroll
    for (int ky = 0; ky < 3; ky++) {
        #pragma unroll
        for (int kx = 0; kx < 3; kx++) {
            int yy = y + ky - 1, xx = x + kx - 1;
            bool ok = (yy >= 0) & (yy < HH) & (xx >= 0) & (xx < WW);
            m[ky * 3 + kx] = ok ? (g_acc[(b << 18) + (yy << 9) + xx] - mean) * inv : 0.f;
        }
    }
    float v[16];
    #pragma unroll
    for (int o = 0; o < 16; o++) {
        float s = sb[o];
        #pragma unroll
        for (int k = 0; k < 9; k++) s = fmaf(sw[o * 9 + k], m[k], s);
        v[o] = fmaxf(s, 0.f);
    }
    uint4* out = (uint4*)(g_h1 + (size_t)p * 16);
    out[0] = make_uint4(pack_h2(v[0], v[1]),  pack_h2(v[2], v[3]),
                        pack_h2(v[4], v[5]),  pack_h2(v[6], v[7]));
    out[1] = make_uint4(pack_h2(v[8], v[9]),  pack_h2(v[10], v[11]),
                        pack_h2(v[12], v[13]), pack_h2(v[14], v[15]));
}

// ---------------- conv2/conv3 via ldmatrix + mma.sync (fp16 in, fp32 acc) ----------------
// RING = 2D+PD+2: write slot (i-1 mod RING) never aliases read slots {i,i+D,i+2D}
// nor in-flight groups -> only ONE barrier per row.
template<int DIL>
__global__ __launch_bounds__(256) void conv16_hmma_kernel()
{
    constexpr int XW = 128, YR = 64, PD = 2;
    constexpr int RING = 2 * DIL + PD + 2;       // 8 (D=2) / 12 (D=4)
    constexpr int SEGPX = XW + 2 * DIL;
    constexpr int SLOTB = SEGPX * 48;

    const __half* __restrict__ in  = (DIL == 2) ? g_h1 : g_h2;
    __half*       __restrict__ out = (DIL == 2) ? g_h2 : g_h1;
    const uint32_t* __restrict__ wF = (DIL == 2) ? g_wF2 : g_wF3;
    const float* __restrict__ sB   = (DIL == 2) ? g_s2  : g_s3;

    extern __shared__ char smem[];
    uint32_t sbase = s2u(smem);
    int tid = threadIdx.x;
    int warp = tid >> 5, lane = tid & 31;
    int x0 = blockIdx.x * XW;
    int y0 = blockIdx.y * YR;
    int b  = blockIdx.z;
    const __half* gin = in + (((size_t)b) << 18) * 16;

    uint32_t bw[9][2][2];
    #pragma unroll
    for (int tap = 0; tap < 9; tap++)
        #pragma unroll
        for (int g = 0; g < 2; g++)
            #pragma unroll
            for (int r = 0; r < 2; r++)
                bw[tap][g][r] = wF[(((tap << 1) + g) << 1 | r) * 32 + lane];

    float bc0[2], bc1[2];
    #pragma unroll
    for (int g = 0; g < 2; g++) {
        int c = (g << 3) + ((lane & 3) << 1);
        bc0[g] = sB[c]; bc1[g] = sB[c + 1];
    }

    int prow = warp * 16 + (lane & 7) + ((lane >> 3) & 1) * 8;
    int sel16 = ((lane >> 4) & 1) * 16;

    auto load_row = [&](int idx) {
        if (idx <= YR - 1 + 2 * DIL) {
            int r = y0 - DIL + idx;
            uint32_t dbase = sbase + (idx % RING) * SLOTB;
            bool rok = (r >= 0) & (r < HH);
            const __half* grow = gin + (((size_t)r) << 9) * 16;
            for (int c = tid; c < SEGPX * 2; c += 256) {
                int s = c >> 1, part = c & 1;
                int x = x0 - DIL + s;
                uint32_t dst = dbase + s * 48 + part * 16;
                if (rok && (unsigned)x < (unsigned)WW)
                    cpasync16(dst, grow + x * 16 + part * 8);
                else
                    sts_zero16(dst);
            }
        }
        cp_commit();
    };

    for (int idx = 0; idx <= 2 * DIL + PD; idx++) load_row(idx);

    for (int i = 0; i < YR; i++) {
        cp_wait<PD>();
        __syncthreads();                           // publishes rows <= i+2D

        load_row(i + 2 * DIL + PD + 1);            // -> slot (i-1)%RING, disjoint from reads

        float d[2][4];
        #pragma unroll
        for (int g = 0; g < 2; g++)
            #pragma unroll
            for (int r = 0; r < 4; r++) d[g][r] = 0.f;

        #pragma unroll
        for (int ky = 0; ky < 3; ky++) {
            uint32_t abase = sbase + ((i + ky * DIL) % RING) * SLOTB;
            #pragma unroll
            for (int kx = 0; kx < 3; kx++) {
                uint32_t a0, a1, a2, a3;
                ldmatrix_x4(a0, a1, a2, a3, abase + (prow + kx * DIL) * 48 + sel16);
                int tap = ky * 3 + kx;
                mma_f16(d[0], a0, a1, a2, a3, bw[tap][0][0], bw[tap][0][1]);
                mma_f16(d[1], a0, a1, a2, a3, bw[tap][1][0], bw[tap][1][1]);
            }
        }

        __half* orow = out + ((((size_t)b << 18) + ((size_t)(y0 + i) << 9) + x0 + warp * 16)) * 16;
        int px = (lane >> 2);
        #pragma unroll
        for (int g = 0; g < 2; g++) {
            int c = (g << 3) + ((lane & 3) << 1);
            uint32_t lo = pack_h2(fmaxf(d[g][0] + bc0[g], 0.f), fmaxf(d[g][1] + bc1[g], 0.f));
            uint32_t hi = pack_h2(fmaxf(d[g][2] + bc0[g], 0.f), fmaxf(d[g][3] + bc1[g], 0.f));
            *(uint32_t*)(orow + px * 16 + c)       = lo;
            *(uint32_t*)(orow + (px + 8) * 16 + c) = hi;
        }
    }
}

// ---------------- final: conv4 1x1 via HMMA + sigmoid + dynamic 3x3 filtering ----------------
// 256 threads = 8 warps; each warp: 16 contiguous pixels of one row. (R7 version)
__global__ __launch_bounds__(256) void final_mma_kernel(
    const float* __restrict__ x, const float* __restrict__ biasp,
    float* __restrict__ out)
{
    __shared__ float sker[8][16][52];   // [warp][px][48 co + pad]

    int tid = threadIdx.x;
    int warp = tid >> 5, lane = tid & 31;
    int pbase = blockIdx.x * 128 + warp * 16;
    int b = pbase >> 18;
    int rem = pbase & (HW - 1);
    int y = rem >> 9, xb0 = rem & 511;

    uint32_t bw[6][2];
    #pragma unroll
    for (int n = 0; n < 6; n++) {
        bw[n][0] = g_wF4[(n * 2 + 0) * 32 + lane];
        bw[n][1] = g_wF4[(n * 2 + 1) * 32 + lane];
    }

    const __half* hb = g_h1 + (size_t)pbase * 16;
    int arow = lane >> 2;
    int cc = (lane & 3) * 2;
    uint32_t a0 = *(const uint32_t*)(hb + arow * 16 + cc);
    uint32_t a1 = *(const uint32_t*)(hb + (arow + 8) * 16 + cc);
    uint32_t a2 = *(const uint32_t*)(hb + arow * 16 + cc + 8);
    uint32_t a3 = *(const uint32_t*)(hb + (arow + 8) * 16 + cc + 8);

    float d[6][4];
    #pragma unroll
    for (int n = 0; n < 6; n++)
        #pragma unroll
        for (int r = 0; r < 4; r++) d[n][r] = 0.f;
    #pragma unroll
    for (int n = 0; n < 6; n++)
        mma_f16(d[n], a0, a1, a2, a3, bw[n][0], bw[n][1]);

    float bias = biasp[0];
    #pragma unroll
    for (int n = 0; n < 6; n++) {
        int col = n * 8 + cc;
        #pragma unroll
        for (int half = 0; half < 2; half++) {
            int px = arow + half * 8;
            float z0 = d[n][half * 2 + 0] + bias;
            float z1 = d[n][half * 2 + 1] + bias;
            float k0 = fmaf(10.f, 1.f / (1.f + __expf(-z0)), 0.1f);
            float k1 = fmaf(10.f, 1.f / (1.f + __expf(-z1)), 0.1f);
            sker[warp][px][col]     = k0;
            sker[warp][px][col + 1] = k1;
        }
    }
    __syncwarp();

    int px = lane & 15;
    int grp = lane >> 4;
    int gx = xb0 + px;
    const float* kp = sker[warp][px];
    int tlo = grp ? 3 : 0;
    int thi = grp ? 5 : 3;
    for (int t = tlo; t < thi; t++) {
        const float* xp = x + ((size_t)(b * TT + t) << 18);
        float o = 0.f;
        #pragma unroll
        for (int dy = 0; dy < 3; dy++) {
            int yy = y + dy - 1;
            bool yok = (yy >= 0) & (yy < HH);
            #pragma unroll
            for (int dx = 0; dx < 3; dx++) {
                int xx = gx + dx - 1;
                bool ok = yok & (xx >= 0) & (xx < WW);
                float xv = ok ? xp[(yy << 9) + xx] : 0.f;
                o = fmaf(kp[t * 9 + dy * 3 + dx], xv, o);
            }
        }
        out[((size_t)(b * TT + t) << 18) + (y << 9) + gx] = o;
    }
}

// ---------------- launch ----------------
extern "C" void kernel_launch(void* const* d_in, const int* in_sizes, int n_in,
                              void* d_out, int out_size)
{
    const float* x_aligned = (const float*)d_in[0];
    const float* raw_diff  = (const float*)d_in[1];
    const float* w1  = (const float*)d_in[2];
    const float* g1  = (const float*)d_in[3];
    const float* b1  = (const float*)d_in[4];
    const float* rm1 = (const float*)d_in[5];
    const float* rv1 = (const float*)d_in[6];
    const float* w2  = (const float*)d_in[7];
    const float* g2  = (const float*)d_in[8];
    const float* b2  = (const float*)d_in[9];
    const float* rm2 = (const float*)d_in[10];
    const float* rv2 = (const float*)d_in[11];
    const float* w3  = (const float*)d_in[12];
    const float* g3  = (const float*)d_in[13];
    const float* b3  = (const float*)d_in[14];
    const float* rm3 = (const float*)d_in[15];
    const float* rv3 = (const float*)d_in[16];
    const float* w4  = (const float*)d_in[17];
    const float* bias = (const float*)d_in[18];
    float* out = (float*)d_out;

    const int SMEM2 = 8  * (132 * 48);   // 50,688 B
    const int SMEM4 = 12 * (136 * 48);   // 78,336 B
    static bool attr_done = false;
    if (!attr_done) {
        cudaFuncSetAttribute(conv16_hmma_kernel<2>, cudaFuncAttributeMaxDynamicSharedMemorySize, SMEM2);
        cudaFuncSetAttribute(conv16_hmma_kernel<4>, cudaFuncAttributeMaxDynamicSharedMemorySize, SMEM4);
        attr_done = true;
    }

    prep_kernel<<<1, 256>>>(w1, g1, b1, rm1, rv1, w2, g2, b2, rm2, rv2,
                            w3, g3, b3, rm3, rv3, w4);
    accum_kernel<<<NPIX / 4 / 256, 256>>>(raw_diff);
    finalize_kernel<<<1, 1>>>();
    conv1_kernel<<<NPIX / 256, 256>>>();
    {
        dim3 grd(WW / 128, HH / 64, BB);   // (4, 8, 8)
        conv16_hmma_kernel<2><<<grd, 256, SMEM2>>>();
        conv16_hmma_kernel<4><<<grd, 256, SMEM4>>>();
    }
    final_mma_kernel<<<NPIX / 128, 256>>>(x_aligned, bias, out);
}

// round 15
// speedup vs baseline: 2.2530x; 1.2051x over previous
#include <cuda_runtime.h>
#include <cuda_fp16.h>
#include <math.h>
#include <stdint.h>

#define BB 8
#define TT 5
#define HH 512
#define WW 512
#define HW (HH*WW)
#define MID 16
#define NPIX (BB*HW)

// ---------------- scratch (no allocation allowed) ----------------
__device__ float  g_acc[NPIX];                    // 8 MB
__device__ __half g_h1[(size_t)NPIX*MID];         // 67 MB
__device__ __half g_h2[(size_t)NPIX*MID];         // 67 MB
__device__ double g_dsum, g_dssq;
__device__ float g_mean, g_inv;
__device__ float g_w1f[144], g_s1[16];
__device__ uint32_t g_wF2[1152];                  // B fragments (half2) conv2
__device__ uint32_t g_wF3[1152];                  // B fragments (half2) conv3
__device__ uint32_t g_wF4[384];                   // B fragments (half2) conv4 1x1 (48-co pad)
__device__ float g_s2[16], g_s3[16];

// ---------------- PTX helpers ----------------
__device__ __forceinline__ uint32_t s2u(const void* p) {
    uint32_t a;
    asm("{ .reg .u64 t; cvta.to.shared.u64 t, %1; cvt.u32.u64 %0, t; }" : "=r"(a) : "l"(p));
    return a;
}
__device__ __forceinline__ void cpasync16(uint32_t dst, const void* src) {
    asm volatile("cp.async.cg.shared.global [%0], [%1], 16;" :: "r"(dst), "l"(src));
}
__device__ __forceinline__ void cp_commit() {
    asm volatile("cp.async.commit_group;" ::: "memory");
}
template<int N> __device__ __forceinline__ void cp_wait() {
    asm volatile("cp.async.wait_group %0;" :: "n"(N) : "memory");
}
__device__ __forceinline__ void sts_zero16(uint32_t dst) {
    asm volatile("st.shared.v4.u32 [%0], {%1,%1,%1,%1};" :: "r"(dst), "r"(0u) : "memory");
}
__device__ __forceinline__ void ldmatrix_x4(uint32_t& r0, uint32_t& r1, uint32_t& r2,
                                            uint32_t& r3, uint32_t addr) {
    asm volatile("ldmatrix.sync.aligned.m8n8.x4.shared.b16 {%0,%1,%2,%3}, [%4];"
                 : "=r"(r0), "=r"(r1), "=r"(r2), "=r"(r3) : "r"(addr));
}
__device__ __forceinline__ void mma_f16(float* d, uint32_t a0, uint32_t a1, uint32_t a2,
                                        uint32_t a3, uint32_t b0, uint32_t b1) {
    asm volatile(
        "mma.sync.aligned.m16n8k16.row.col.f32.f16.f16.f32 "
        "{%0,%1,%2,%3}, {%4,%5,%6,%7}, {%8,%9}, {%0,%1,%2,%3};"
        : "+f"(d[0]), "+f"(d[1]), "+f"(d[2]), "+f"(d[3])
        : "r"(a0), "r"(a1), "r"(a2), "r"(a3), "r"(b0), "r"(b1));
}
__device__ __forceinline__ uint32_t pack_h2(float a, float b) {
    __half2 h = __floats2half2_rn(a, b);
    return *reinterpret_cast<uint32_t*>(&h);
}
__device__ __forceinline__ float tanh_approx(float z) {
    float r;
    asm("tanh.approx.f32 %0, %1;" : "=f"(r) : "f"(z));
    return r;
}

// ---------------- prep: fold BN into conv weights, build B fragments ----------------
__global__ void prep_kernel(
    const float* __restrict__ w1, const float* __restrict__ g1, const float* __restrict__ b1,
    const float* __restrict__ rm1, const float* __restrict__ rv1,
    const float* __restrict__ w2, const float* __restrict__ g2, const float* __restrict__ b2,
    const float* __restrict__ rm2, const float* __restrict__ rv2,
    const float* __restrict__ w3, const float* __restrict__ g3, const float* __restrict__ b3,
    const float* __restrict__ rm3, const float* __restrict__ rv3,
    const float* __restrict__ w4)
{
    int tid = threadIdx.x;
    if (tid == 0) { g_dsum = 0.0; g_dssq = 0.0; }

    for (int i = tid; i < 144; i += 256) {
        int o = i / 9, k = i % 9;
        float sc = g1[o] / sqrtf(rv1[o] + 1e-5f);
        float s = 0.f;
        #pragma unroll
        for (int t = 0; t < TT; t++) s += w1[(o * TT + t) * 9 + k];
        g_w1f[i] = sc * s;
    }
    if (tid < 16) {
        float sc1 = g1[tid] / sqrtf(rv1[tid] + 1e-5f);
        g_s1[tid] = b1[tid] - rm1[tid] * sc1;
        float sc2 = g2[tid] / sqrtf(rv2[tid] + 1e-5f);
        g_s2[tid] = b2[tid] - rm2[tid] * sc2;
        float sc3 = g3[tid] / sqrtf(rv3[tid] + 1e-5f);
        g_s3[tid] = b3[tid] - rm3[tid] * sc3;
    }
    for (int i = tid; i < 1152; i += 256) {
        int t = i & 31, r = (i >> 5) & 1, g = (i >> 6) & 1, tap = i >> 7;
        int co = (g << 3) + (t >> 2);
        int k0 = (t & 3) * 2 + (r << 3);
        float sc2 = g2[co] / sqrtf(rv2[co] + 1e-5f);
        g_wF2[i] = pack_h2(sc2 * w2[((co * 16 + k0) * 9) + tap],
                           sc2 * w2[((co * 16 + k0 + 1) * 9) + tap]);
        float sc3 = g3[co] / sqrtf(rv3[co] + 1e-5f);
        g_wF3[i] = pack_h2(sc3 * w3[((co * 16 + k0) * 9) + tap],
                           sc3 * w3[((co * 16 + k0 + 1) * 9) + tap]);
    }
    for (int i = tid; i < 384; i += 256) {
        int t = i & 31, r = (i >> 5) & 1, n = i >> 6;
        int co = (n << 3) + (t >> 2);
        int k0 = (t & 3) * 2 + (r << 3);
        float v0 = (co < 45) ? w4[co * 16 + k0]     : 0.f;
        float v1 = (co < 45) ? w4[co * 16 + k0 + 1] : 0.f;
        g_wF4[i] = pack_h2(v0, v1);
    }
}

// ---------------- acc = sum|raw_diff| + mean/var reduction ----------------
__global__ void accum_kernel(const float* __restrict__ rd)
{
    int i = blockIdx.x * 256 + threadIdx.x;
    int b = i >> 16;
    int r = i & 65535;
    const float4* p = (const float4*)rd;
    float4 a = make_float4(0.f, 0.f, 0.f, 0.f);
    #pragma unroll
    for (int t = 0; t < TT - 1; t++) {
        float4 v = p[((size_t)(b * (TT - 1) + t)) * 65536 + r];
        a.x += fabsf(v.x); a.y += fabsf(v.y); a.z += fabsf(v.z); a.w += fabsf(v.w);
    }
    ((float4*)g_acc)[i] = a;

    double ls  = (double)a.x + (double)a.y + (double)a.z + (double)a.w;
    double lss = (double)a.x * a.x + (double)a.y * a.y + (double)a.z * a.z + (double)a.w * a.w;
    #pragma unroll
    for (int o = 16; o > 0; o >>= 1) {
        ls  += __shfl_down_sync(0xffffffffu, ls,  o);
        lss += __shfl_down_sync(0xffffffffu, lss, o);
    }
    __shared__ double ss[8], sq[8];
    int wid = threadIdx.x >> 5, lane = threadIdx.x & 31;
    if (lane == 0) { ss[wid] = ls; sq[wid] = lss; }
    __syncthreads();
    if (threadIdx.x == 0) {
        double s = 0.0, q = 0.0;
        #pragma unroll
        for (int w = 0; w < 8; w++) { s += ss[w]; q += sq[w]; }
        atomicAdd(&g_dsum, s);
        atomicAdd(&g_dssq, q);
    }
}

__global__ void finalize_kernel()
{
    double n = (double)NPIX;
    double mean = g_dsum / n;
    double var = (g_dssq - g_dsum * g_dsum / n) / (n - 1.0);
    double sd = sqrt(var);
    g_mean = (float)mean;
    g_inv = (float)(1.0 / (sd + 1e-6));
}

// ---------------- conv1: 1->16 chan, 3x3 d1, fp16 NHWC output ----------------
__global__ void conv1_kernel()
{
    __shared__ float sw[144], sb[16];
    int tid = threadIdx.x;
    if (tid < 144) sw[tid] = g_w1f[tid];
    if (tid < 16)  sb[tid] = g_s1[tid];
    __syncthreads();

    int p = blockIdx.x * 256 + tid;
    int b = p >> 18;
    int rem = p & (HW - 1);
    int y = rem >> 9, x = rem & 511;
    float mean = g_mean, inv = g_inv;

    float m[9];
    #pragma unroll
    for (int ky = 0; ky < 3; ky++) {
        #pragma unroll
        for (int kx = 0; kx < 3; kx++) {
            int yy = y + ky - 1, xx = x + kx - 1;
            bool ok = (yy >= 0) & (yy < HH) & (xx >= 0) & (xx < WW);
            m[ky * 3 + kx] = ok ? (g_acc[(b << 18) + (yy << 9) + xx] - mean) * inv : 0.f;
        }
    }
    float v[16];
    #pragma unroll
    for (int o = 0; o < 16; o++) {
        float s = sb[o];
        #pragma unroll
        for (int k = 0; k < 9; k++) s = fmaf(sw[o * 9 + k], m[k], s);
        v[o] = fmaxf(s, 0.f);
    }
    uint4* out = (uint4*)(g_h1 + (size_t)p * 16);
    out[0] = make_uint4(pack_h2(v[0], v[1]),  pack_h2(v[2], v[3]),
                        pack_h2(v[4], v[5]),  pack_h2(v[6], v[7]));
    out[1] = make_uint4(pack_h2(v[8], v[9]),  pack_h2(v[10], v[11]),
                        pack_h2(v[12], v[13]), pack_h2(v[14], v[15]));
}

// ---------------- conv2/conv3 via ldmatrix + mma.sync (fp16 in, fp32 acc) ----------------
// RING = 2D+PD+2 -> single barrier per row.
template<int DIL>
__global__ __launch_bounds__(256) void conv16_hmma_kernel()
{
    constexpr int XW = 128, YR = 64, PD = 2;
    constexpr int RING = 2 * DIL + PD + 2;       // 8 (D=2) / 12 (D=4)
    constexpr int SEGPX = XW + 2 * DIL;
    constexpr int SLOTB = SEGPX * 48;

    const __half* __restrict__ in  = (DIL == 2) ? g_h1 : g_h2;
    __half*       __restrict__ out = (DIL == 2) ? g_h2 : g_h1;
    const uint32_t* __restrict__ wF = (DIL == 2) ? g_wF2 : g_wF3;
    const float* __restrict__ sB   = (DIL == 2) ? g_s2  : g_s3;

    extern __shared__ char smem[];
    uint32_t sbase = s2u(smem);
    int tid = threadIdx.x;
    int warp = tid >> 5, lane = tid & 31;
    int x0 = blockIdx.x * XW;
    int y0 = blockIdx.y * YR;
    int b  = blockIdx.z;
    const __half* gin = in + (((size_t)b) << 18) * 16;

    uint32_t bw[9][2][2];
    #pragma unroll
    for (int tap = 0; tap < 9; tap++)
        #pragma unroll
        for (int g = 0; g < 2; g++)
            #pragma unroll
            for (int r = 0; r < 2; r++)
                bw[tap][g][r] = wF[(((tap << 1) + g) << 1 | r) * 32 + lane];

    float bc0[2], bc1[2];
    #pragma unroll
    for (int g = 0; g < 2; g++) {
        int c = (g << 3) + ((lane & 3) << 1);
        bc0[g] = sB[c]; bc1[g] = sB[c + 1];
    }

    int prow = warp * 16 + (lane & 7) + ((lane >> 3) & 1) * 8;
    int sel16 = ((lane >> 4) & 1) * 16;

    auto load_row = [&](int idx) {
        if (idx <= YR - 1 + 2 * DIL) {
            int r = y0 - DIL + idx;
            uint32_t dbase = sbase + (idx % RING) * SLOTB;
            bool rok = (r >= 0) & (r < HH);
            const __half* grow = gin + (((size_t)r) << 9) * 16;
            for (int c = tid; c < SEGPX * 2; c += 256) {
                int s = c >> 1, part = c & 1;
                int x = x0 - DIL + s;
                uint32_t dst = dbase + s * 48 + part * 16;
                if (rok && (unsigned)x < (unsigned)WW)
                    cpasync16(dst, grow + x * 16 + part * 8);
                else
                    sts_zero16(dst);
            }
        }
        cp_commit();
    };

    for (int idx = 0; idx <= 2 * DIL + PD; idx++) load_row(idx);

    for (int i = 0; i < YR; i++) {
        cp_wait<PD>();
        __syncthreads();                           // publishes rows <= i+2D

        load_row(i + 2 * DIL + PD + 1);            // -> slot (i-1)%RING, disjoint from reads

        float d[2][4];
        #pragma unroll
        for (int g = 0; g < 2; g++)
            #pragma unroll
            for (int r = 0; r < 4; r++) d[g][r] = 0.f;

        #pragma unroll
        for (int ky = 0; ky < 3; ky++) {
            uint32_t abase = sbase + ((i + ky * DIL) % RING) * SLOTB;
            #pragma unroll
            for (int kx = 0; kx < 3; kx++) {
                uint32_t a0, a1, a2, a3;
                ldmatrix_x4(a0, a1, a2, a3, abase + (prow + kx * DIL) * 48 + sel16);
                int tap = ky * 3 + kx;
                mma_f16(d[0], a0, a1, a2, a3, bw[tap][0][0], bw[tap][0][1]);
                mma_f16(d[1], a0, a1, a2, a3, bw[tap][1][0], bw[tap][1][1]);
            }
        }

        __half* orow = out + ((((size_t)b << 18) + ((size_t)(y0 + i) << 9) + x0 + warp * 16)) * 16;
        int px = (lane >> 2);
        #pragma unroll
        for (int g = 0; g < 2; g++) {
            int c = (g << 3) + ((lane & 3) << 1);
            uint32_t lo = pack_h2(fmaxf(d[g][0] + bc0[g], 0.f), fmaxf(d[g][1] + bc1[g], 0.f));
            uint32_t hi = pack_h2(fmaxf(d[g][2] + bc0[g], 0.f), fmaxf(d[g][3] + bc1[g], 0.f));
            *(uint32_t*)(orow + px * 16 + c)       = lo;
            *(uint32_t*)(orow + (px + 8) * 16 + c) = hi;
        }
    }
}

// ---------------- final: conv4 1x1 HMMA + tanh-sigmoid + coalesced dyn filtering ----------
// Phase 1: per-warp MMA + sigmoid into sker[8][16][53] (pad-53 -> conflict-free reads).
// Phase 2 (after block barrier): 20 warp-tasks = 5 t-planes x 4 segments of 32 px;
// all lanes of a warp in ONE t-plane over consecutive px -> minimal LDG wavefronts.
__global__ __launch_bounds__(256) void final_mma_kernel(
    const float* __restrict__ x, const float* __restrict__ biasp,
    float* __restrict__ out)
{
    __shared__ float sker[8][16][53];   // 27,136 B

    int tid = threadIdx.x;
    int warp = tid >> 5, lane = tid & 31;
    int pbase = blockIdx.x * 128 + warp * 16;
    int b = pbase >> 18;
    int rem0 = (blockIdx.x * 128) & (HW - 1);
    int y = rem0 >> 9, xblk = rem0 & 511;

    // ---- phase 1: conv4 MMA + sigmoid ----
    uint32_t bw[6][2];
    #pragma unroll
    for (int n = 0; n < 6; n++) {
        bw[n][0] = g_wF4[(n * 2 + 0) * 32 + lane];
        bw[n][1] = g_wF4[(n * 2 + 1) * 32 + lane];
    }

    const __half* hb = g_h1 + (size_t)pbase * 16;
    int arow = lane >> 2;
    int cc = (lane & 3) * 2;
    uint32_t a0 = *(const uint32_t*)(hb + arow * 16 + cc);
    uint32_t a1 = *(const uint32_t*)(hb + (arow + 8) * 16 + cc);
    uint32_t a2 = *(const uint32_t*)(hb + arow * 16 + cc + 8);
    uint32_t a3 = *(const uint32_t*)(hb + (arow + 8) * 16 + cc + 8);

    float d[6][4];
    #pragma unroll
    for (int n = 0; n < 6; n++)
        #pragma unroll
        for (int r = 0; r < 4; r++) d[n][r] = 0.f;
    #pragma unroll
    for (int n = 0; n < 6; n++)
        mma_f16(d[n], a0, a1, a2, a3, bw[n][0], bw[n][1]);

    float bias = biasp[0];
    // 10*sigmoid(z)+0.1 = 5*tanh(z/2) + 5.1  (one MUFU per value)
    #pragma unroll
    for (int n = 0; n < 6; n++) {
        int col = n * 8 + cc;
        if (col < 45) {
            #pragma unroll
            for (int half = 0; half < 2; half++) {
                int px = arow + half * 8;
                float k0 = fmaf(5.f, tanh_approx((d[n][half * 2 + 0] + bias) * 0.5f), 5.1f);
                float k1 = fmaf(5.f, tanh_approx((d[n][half * 2 + 1] + bias) * 0.5f), 5.1f);
                sker[warp][px][col] = k0;
                if (col + 1 < 45) sker[warp][px][col + 1] = k1;
            }
        }
    }
    __syncthreads();

    // ---- phase 2: dynamic filtering, warp-contained t-planes ----
    for (int task = warp; task < 20; task += 8) {
        int t = task >> 2;           // 0..4
        int seg = task & 3;          // 0..3
        int pxl = seg * 32 + lane;   // 0..127
        int gx = xblk + pxl;
        const float* kp = &sker[pxl >> 4][pxl & 15][t * 9];
        const float* xp = x + ((size_t)(b * TT + t) << 18);

        float w[9];
        #pragma unroll
        for (int j = 0; j < 9; j++) w[j] = kp[j];

        float o = 0.f;
        #pragma unroll
        for (int dy = 0; dy < 3; dy++) {
            int yy = y + dy - 1;
            bool yok = (yy >= 0) & (yy < HH);
            const float* row = xp + (yy << 9);
            #pragma unroll
            for (int dx = 0; dx < 3; dx++) {
                int xx = gx + dx - 1;
                bool ok = yok & (xx >= 0) & (xx < WW);
                float xv = ok ? row[xx] : 0.f;
                o = fmaf(w[dy * 3 + dx], xv, o);
            }
        }
        out[((size_t)(b * TT + t) << 18) + (y << 9) + gx] = o;
    }
}

// ---------------- launch ----------------
extern "C" void kernel_launch(void* const* d_in, const int* in_sizes, int n_in,
                              void* d_out, int out_size)
{
    const float* x_aligned = (const float*)d_in[0];
    const float* raw_diff  = (const float*)d_in[1];
    const float* w1  = (const float*)d_in[2];
    const float* g1  = (const float*)d_in[3];
    const float* b1  = (const float*)d_in[4];
    const float* rm1 = (const float*)d_in[5];
    const float* rv1 = (const float*)d_in[6];
    const float* w2  = (const float*)d_in[7];
    const float* g2  = (const float*)d_in[8];
    const float* b2  = (const float*)d_in[9];
    const float* rm2 = (const float*)d_in[10];
    const float* rv2 = (const float*)d_in[11];
    const float* w3  = (const float*)d_in[12];
    const float* g3  = (const float*)d_in[13];
    const float* b3  = (const float*)d_in[14];
    const float* rm3 = (const float*)d_in[15];
    const float* rv3 = (const float*)d_in[16];
    const float* w4  = (const float*)d_in[17];
    const float* bias = (const float*)d_in[18];
    float* out = (float*)d_out;

    const int SMEM2 = 8  * (132 * 48);   // 50,688 B
    const int SMEM4 = 12 * (136 * 48);   // 78,336 B
    static bool attr_done = false;
    if (!attr_done) {
        cudaFuncSetAttribute(conv16_hmma_kernel<2>, cudaFuncAttributeMaxDynamicSharedMemorySize, SMEM2);
        cudaFuncSetAttribute(conv16_hmma_kernel<4>, cudaFuncAttributeMaxDynamicSharedMemorySize, SMEM4);
        attr_done = true;
    }

    prep_kernel<<<1, 256>>>(w1, g1, b1, rm1, rv1, w2, g2, b2, rm2, rv2,
                            w3, g3, b3, rm3, rv3, w4);
    accum_kernel<<<NPIX / 4 / 256, 256>>>(raw_diff);
    finalize_kernel<<<1, 1>>>();
    conv1_kernel<<<NPIX / 256, 256>>>();
    {
        dim3 grd(WW / 128, HH / 64, BB);   // (4, 8, 8)
        conv16_hmma_kernel<2><<<grd, 256, SMEM2>>>();
        conv16_hmma_kernel<4><<<grd, 256, SMEM4>>>();
    }
    final_mma_kernel<<<NPIX / 128, 256>>>(x_aligned, bias, out);
}

// round 16
// speedup vs baseline: 2.3652x; 1.0498x over previous
#include <cuda_runtime.h>
#include <cuda_fp16.h>
#include <math.h>
#include <stdint.h>

#define BB 8
#define TT 5
#define HH 512
#define WW 512
#define HW (HH*WW)
#define MID 16
#define NPIX (BB*HW)

// ---------------- scratch (no allocation allowed) ----------------
__device__ float  g_acc[NPIX];                    // 8 MB
__device__ __half g_h1[(size_t)NPIX*MID];         // 67 MB
__device__ __half g_h2[(size_t)NPIX*MID];         // 67 MB
__device__ double g_dsum, g_dssq;
__device__ float g_mean, g_inv;
__device__ uint32_t g_w1h[72];                    // conv1 weights half2 [k][jpair]
__device__ uint32_t g_s1h[8];                     // conv1 bias half2 [jpair]
__device__ uint32_t g_wF2[1152];                  // B fragments (half2) conv2
__device__ uint32_t g_wF3[1152];                  // B fragments (half2) conv3
__device__ uint32_t g_wF4[384];                   // B fragments (half2) conv4 1x1 (48-co pad)
__device__ float g_s2[16], g_s3[16];

// ---------------- PTX helpers ----------------
__device__ __forceinline__ uint32_t s2u(const void* p) {
    uint32_t a;
    asm("{ .reg .u64 t; cvta.to.shared.u64 t, %1; cvt.u32.u64 %0, t; }" : "=r"(a) : "l"(p));
    return a;
}
__device__ __forceinline__ void cpasync16(uint32_t dst, const void* src) {
    asm volatile("cp.async.cg.shared.global [%0], [%1], 16;" :: "r"(dst), "l"(src));
}
__device__ __forceinline__ void cp_commit() {
    asm volatile("cp.async.commit_group;" ::: "memory");
}
template<int N> __device__ __forceinline__ void cp_wait() {
    asm volatile("cp.async.wait_group %0;" :: "n"(N) : "memory");
}
__device__ __forceinline__ void sts_zero16(uint32_t dst) {
    asm volatile("st.shared.v4.u32 [%0], {%1,%1,%1,%1};" :: "r"(dst), "r"(0u) : "memory");
}
__device__ __forceinline__ void ldmatrix_x4(uint32_t& r0, uint32_t& r1, uint32_t& r2,
                                            uint32_t& r3, uint32_t addr) {
    asm volatile("ldmatrix.sync.aligned.m8n8.x4.shared.b16 {%0,%1,%2,%3}, [%4];"
                 : "=r"(r0), "=r"(r1), "=r"(r2), "=r"(r3) : "r"(addr));
}
__device__ __forceinline__ void mma_f16(float* d, uint32_t a0, uint32_t a1, uint32_t a2,
                                        uint32_t a3, uint32_t b0, uint32_t b1) {
    asm volatile(
        "mma.sync.aligned.m16n8k16.row.col.f32.f16.f16.f32 "
        "{%0,%1,%2,%3}, {%4,%5,%6,%7}, {%8,%9}, {%0,%1,%2,%3};"
        : "+f"(d[0]), "+f"(d[1]), "+f"(d[2]), "+f"(d[3])
        : "r"(a0), "r"(a1), "r"(a2), "r"(a3), "r"(b0), "r"(b1));
}
__device__ __forceinline__ uint32_t pack_h2(float a, float b) {
    __half2 h = __floats2half2_rn(a, b);
    return *reinterpret_cast<uint32_t*>(&h);
}
__device__ __forceinline__ float tanh_approx(float z) {
    float r;
    asm("tanh.approx.f32 %0, %1;" : "=f"(r) : "f"(z));
    return r;
}

// ---------------- prep: fold BN into conv weights, build fragments ----------------
__global__ void prep_kernel(
    const float* __restrict__ w1, const float* __restrict__ g1, const float* __restrict__ b1,
    const float* __restrict__ rm1, const float* __restrict__ rv1,
    const float* __restrict__ w2, const float* __restrict__ g2, const float* __restrict__ b2,
    const float* __restrict__ rm2, const float* __restrict__ rv2,
    const float* __restrict__ w3, const float* __restrict__ g3, const float* __restrict__ b3,
    const float* __restrict__ rm3, const float* __restrict__ rv3,
    const float* __restrict__ w4)
{
    int tid = threadIdx.x;
    if (tid == 0) { g_dsum = 0.0; g_dssq = 0.0; }

    // conv1 weights: half2 channel pairs, BN-folded, T-summed
    for (int i = tid; i < 72; i += 256) {
        int k = i / 8, j = i % 8;
        float v[2];
        #pragma unroll
        for (int h = 0; h < 2; h++) {
            int o = 2 * j + h;
            float sc = g1[o] / sqrtf(rv1[o] + 1e-5f);
            float s = 0.f;
            #pragma unroll
            for (int t = 0; t < TT; t++) s += w1[(o * TT + t) * 9 + k];
            v[h] = sc * s;
        }
        g_w1h[i] = pack_h2(v[0], v[1]);
    }
    if (tid < 8) {
        float v[2];
        #pragma unroll
        for (int h = 0; h < 2; h++) {
            int o = 2 * tid + h;
            float sc = g1[o] / sqrtf(rv1[o] + 1e-5f);
            v[h] = b1[o] - rm1[o] * sc;
        }
        g_s1h[tid] = pack_h2(v[0], v[1]);
    }
    if (tid < 16) {
        float sc2 = g2[tid] / sqrtf(rv2[tid] + 1e-5f);
        g_s2[tid] = b2[tid] - rm2[tid] * sc2;
        float sc3 = g3[tid] / sqrtf(rv3[tid] + 1e-5f);
        g_s3[tid] = b3[tid] - rm3[tid] * sc3;
    }
    for (int i = tid; i < 1152; i += 256) {
        int t = i & 31, r = (i >> 5) & 1, g = (i >> 6) & 1, tap = i >> 7;
        int co = (g << 3) + (t >> 2);
        int k0 = (t & 3) * 2 + (r << 3);
        float sc2 = g2[co] / sqrtf(rv2[co] + 1e-5f);
        g_wF2[i] = pack_h2(sc2 * w2[((co * 16 + k0) * 9) + tap],
                           sc2 * w2[((co * 16 + k0 + 1) * 9) + tap]);
        float sc3 = g3[co] / sqrtf(rv3[co] + 1e-5f);
        g_wF3[i] = pack_h2(sc3 * w3[((co * 16 + k0) * 9) + tap],
                           sc3 * w3[((co * 16 + k0 + 1) * 9) + tap]);
    }
    for (int i = tid; i < 384; i += 256) {
        int t = i & 31, r = (i >> 5) & 1, n = i >> 6;
        int co = (n << 3) + (t >> 2);
        int k0 = (t & 3) * 2 + (r << 3);
        float v0 = (co < 45) ? w4[co * 16 + k0]     : 0.f;
        float v1 = (co < 45) ? w4[co * 16 + k0 + 1] : 0.f;
        g_wF4[i] = pack_h2(v0, v1);
    }
}

// ---------------- acc = sum|raw_diff| + mean/var reduction ----------------
__global__ void accum_kernel(const float* __restrict__ rd)
{
    int i = blockIdx.x * 256 + threadIdx.x;
    int b = i >> 16;
    int r = i & 65535;
    const float4* p = (const float4*)rd;
    float4 a = make_float4(0.f, 0.f, 0.f, 0.f);
    #pragma unroll
    for (int t = 0; t < TT - 1; t++) {
        float4 v = p[((size_t)(b * (TT - 1) + t)) * 65536 + r];
        a.x += fabsf(v.x); a.y += fabsf(v.y); a.z += fabsf(v.z); a.w += fabsf(v.w);
    }
    ((float4*)g_acc)[i] = a;

    double ls  = (double)a.x + (double)a.y + (double)a.z + (double)a.w;
    double lss = (double)a.x * a.x + (double)a.y * a.y + (double)a.z * a.z + (double)a.w * a.w;
    #pragma unroll
    for (int o = 16; o > 0; o >>= 1) {
        ls  += __shfl_down_sync(0xffffffffu, ls,  o);
        lss += __shfl_down_sync(0xffffffffu, lss, o);
    }
    __shared__ double ss[8], sq[8];
    int wid = threadIdx.x >> 5, lane = threadIdx.x & 31;
    if (lane == 0) { ss[wid] = ls; sq[wid] = lss; }
    __syncthreads();
    if (threadIdx.x == 0) {
        double s = 0.0, q = 0.0;
        #pragma unroll
        for (int w = 0; w < 8; w++) { s += ss[w]; q += sq[w]; }
        atomicAdd(&g_dsum, s);
        atomicAdd(&g_dssq, q);
    }
}

__global__ void finalize_kernel()
{
    double n = (double)NPIX;
    double mean = g_dsum / n;
    double var = (g_dssq - g_dsum * g_dsum / n) / (n - 1.0);
    double sd = sqrt(var);
    g_mean = (float)mean;
    g_inv = (float)(1.0 / (sd + 1e-6));
}

// ---------------- conv1: 1->16 chan, 3x3 d1, HFMA2 channel pairs ----------------
__global__ void conv1_kernel()
{
    __shared__ uint32_t sw[72];
    __shared__ uint32_t sb[8];
    int tid = threadIdx.x;
    if (tid < 72) sw[tid] = g_w1h[tid];
    if (tid < 8)  sb[tid] = g_s1h[tid];
    __syncthreads();

    int p = blockIdx.x * 256 + tid;
    int b = p >> 18;
    int rem = p & (HW - 1);
    int y = rem >> 9, x = rem & 511;
    float mean = g_mean, inv = g_inv;

    float m[9];
    #pragma unroll
    for (int ky = 0; ky < 3; ky++) {
        #pragma unroll
        for (int kx = 0; kx < 3; kx++) {
            int yy = y + ky - 1, xx = x + kx - 1;
            bool ok = (yy >= 0) & (yy < HH) & (xx >= 0) & (xx < WW);
            m[ky * 3 + kx] = ok ? (g_acc[(b << 18) + (yy << 9) + xx] - mean) * inv : 0.f;
        }
    }

    __half2 v[8];
    #pragma unroll
    for (int j = 0; j < 8; j++) v[j] = *reinterpret_cast<__half2*>(&sb[j]);
    #pragma unroll
    for (int k = 0; k < 9; k++) {
        __half2 mk = __float2half2_rn(m[k]);
        const __half2* wk = reinterpret_cast<const __half2*>(sw + k * 8);
        #pragma unroll
        for (int j = 0; j < 8; j++) v[j] = __hfma2(wk[j], mk, v[j]);
    }
    __half2 z = __float2half2_rn(0.f);
    uint32_t u[8];
    #pragma unroll
    for (int j = 0; j < 8; j++) {
        __half2 r = __hmax2(v[j], z);
        u[j] = *reinterpret_cast<uint32_t*>(&r);
    }

    uint4* out = (uint4*)(g_h1 + (size_t)p * 16);
    out[0] = make_uint4(u[0], u[1], u[2], u[3]);
    out[1] = make_uint4(u[4], u[5], u[6], u[7]);
}

// ---------------- conv2/conv3 via ldmatrix + mma.sync (fp16 in, fp32 acc) ----------------
// RING = 2D+PD+2 -> single barrier per row.
template<int DIL>
__global__ __launch_bounds__(256) void conv16_hmma_kernel()
{
    constexpr int XW = 128, YR = 64, PD = 2;
    constexpr int RING = 2 * DIL + PD + 2;       // 8 (D=2) / 12 (D=4)
    constexpr int SEGPX = XW + 2 * DIL;
    constexpr int SLOTB = SEGPX * 48;

    const __half* __restrict__ in  = (DIL == 2) ? g_h1 : g_h2;
    __half*       __restrict__ out = (DIL == 2) ? g_h2 : g_h1;
    const uint32_t* __restrict__ wF = (DIL == 2) ? g_wF2 : g_wF3;
    const float* __restrict__ sB   = (DIL == 2) ? g_s2  : g_s3;

    extern __shared__ char smem[];
    uint32_t sbase = s2u(smem);
    int tid = threadIdx.x;
    int warp = tid >> 5, lane = tid & 31;
    int x0 = blockIdx.x * XW;
    int y0 = blockIdx.y * YR;
    int b  = blockIdx.z;
    const __half* gin = in + (((size_t)b) << 18) * 16;

    uint32_t bw[9][2][2];
    #pragma unroll
    for (int tap = 0; tap < 9; tap++)
        #pragma unroll
        for (int g = 0; g < 2; g++)
            #pragma unroll
            for (int r = 0; r < 2; r++)
                bw[tap][g][r] = wF[(((tap << 1) + g) << 1 | r) * 32 + lane];

    float bc0[2], bc1[2];
    #pragma unroll
    for (int g = 0; g < 2; g++) {
        int c = (g << 3) + ((lane & 3) << 1);
        bc0[g] = sB[c]; bc1[g] = sB[c + 1];
    }

    int prow = warp * 16 + (lane & 7) + ((lane >> 3) & 1) * 8;
    int sel16 = ((lane >> 4) & 1) * 16;

    auto load_row = [&](int idx) {
        if (idx <= YR - 1 + 2 * DIL) {
            int r = y0 - DIL + idx;
            uint32_t dbase = sbase + (idx % RING) * SLOTB;
            bool rok = (r >= 0) & (r < HH);
            const __half* grow = gin + (((size_t)r) << 9) * 16;
            for (int c = tid; c < SEGPX * 2; c += 256) {
                int s = c >> 1, part = c & 1;
                int x = x0 - DIL + s;
                uint32_t dst = dbase + s * 48 + part * 16;
                if (rok && (unsigned)x < (unsigned)WW)
                    cpasync16(dst, grow + x * 16 + part * 8);
                else
                    sts_zero16(dst);
            }
        }
        cp_commit();
    };

    for (int idx = 0; idx <= 2 * DIL + PD; idx++) load_row(idx);

    for (int i = 0; i < YR; i++) {
        cp_wait<PD>();
        __syncthreads();                           // publishes rows <= i+2D

        load_row(i + 2 * DIL + PD + 1);            // -> slot (i-1)%RING, disjoint from reads

        float d[2][4];
        #pragma unroll
        for (int g = 0; g < 2; g++)
            #pragma unroll
            for (int r = 0; r < 4; r++) d[g][r] = 0.f;

        #pragma unroll
        for (int ky = 0; ky < 3; ky++) {
            uint32_t abase = sbase + ((i + ky * DIL) % RING) * SLOTB;
            #pragma unroll
            for (int kx = 0; kx < 3; kx++) {
                uint32_t a0, a1, a2, a3;
                ldmatrix_x4(a0, a1, a2, a3, abase + (prow + kx * DIL) * 48 + sel16);
                int tap = ky * 3 + kx;
                mma_f16(d[0], a0, a1, a2, a3, bw[tap][0][0], bw[tap][0][1]);
                mma_f16(d[1], a0, a1, a2, a3, bw[tap][1][0], bw[tap][1][1]);
            }
        }

        __half* orow = out + ((((size_t)b << 18) + ((size_t)(y0 + i) << 9) + x0 + warp * 16)) * 16;
        int px = (lane >> 2);
        #pragma unroll
        for (int g = 0; g < 2; g++) {
            int c = (g << 3) + ((lane & 3) << 1);
            uint32_t lo = pack_h2(fmaxf(d[g][0] + bc0[g], 0.f), fmaxf(d[g][1] + bc1[g], 0.f));
            uint32_t hi = pack_h2(fmaxf(d[g][2] + bc0[g], 0.f), fmaxf(d[g][3] + bc1[g], 0.f));
            *(uint32_t*)(orow + px * 16 + c)       = lo;
            *(uint32_t*)(orow + (px + 8) * 16 + c) = hi;
        }
    }
}

// ---------------- final: conv4 1x1 HMMA + tanh-sigmoid + coalesced dyn filtering ----------
// 320 threads. Phase 1 (warps 0-7): MMA + sigmoid into sker[8][16][53].
// Phase 2 (all 10 warps): exactly 2 warp-tasks each of 20 (5 t-planes x 4 segments).
__global__ __launch_bounds__(320) void final_mma_kernel(
    const float* __restrict__ x, const float* __restrict__ biasp,
    float* __restrict__ out)
{
    __shared__ float sker[8][16][53];   // 27,136 B

    int tid = threadIdx.x;
    int warp = tid >> 5, lane = tid & 31;
    int rem0 = (blockIdx.x * 128) & (HW - 1);
    int b = (blockIdx.x * 128) >> 18;
    int y = rem0 >> 9, xblk = rem0 & 511;

    if (warp < 8) {
        int pbase = blockIdx.x * 128 + warp * 16;
        uint32_t bw[6][2];
        #pragma unroll
        for (int n = 0; n < 6; n++) {
            bw[n][0] = g_wF4[(n * 2 + 0) * 32 + lane];
            bw[n][1] = g_wF4[(n * 2 + 1) * 32 + lane];
        }

        const __half* hb = g_h1 + (size_t)pbase * 16;
        int arow = lane >> 2;
        int cc = (lane & 3) * 2;
        uint32_t a0 = *(const uint32_t*)(hb + arow * 16 + cc);
        uint32_t a1 = *(const uint32_t*)(hb + (arow + 8) * 16 + cc);
        uint32_t a2 = *(const uint32_t*)(hb + arow * 16 + cc + 8);
        uint32_t a3 = *(const uint32_t*)(hb + (arow + 8) * 16 + cc + 8);

        float d[6][4];
        #pragma unroll
        for (int n = 0; n < 6; n++)
            #pragma unroll
            for (int r = 0; r < 4; r++) d[n][r] = 0.f;
        #pragma unroll
        for (int n = 0; n < 6; n++)
            mma_f16(d[n], a0, a1, a2, a3, bw[n][0], bw[n][1]);

        float bias = biasp[0];
        // 10*sigmoid(z)+0.1 = 5*tanh(z/2) + 5.1
        #pragma unroll
        for (int n = 0; n < 6; n++) {
            int col = n * 8 + cc;
            if (col < 45) {
                #pragma unroll
                for (int half = 0; half < 2; half++) {
                    int px = arow + half * 8;
                    float k0 = fmaf(5.f, tanh_approx((d[n][half * 2 + 0] + bias) * 0.5f), 5.1f);
                    float k1 = fmaf(5.f, tanh_approx((d[n][half * 2 + 1] + bias) * 0.5f), 5.1f);
                    sker[warp][px][col] = k0;
                    if (col + 1 < 45) sker[warp][px][col + 1] = k1;
                }
            }
        }
    }
    __syncthreads();

    // ---- phase 2: 20 tasks on 10 warps = 2 each ----
    #pragma unroll
    for (int pass = 0; pass < 2; pass++) {
        int task = warp + pass * 10;
        int t = task >> 2;           // 0..4
        int seg = task & 3;          // 0..3
        int pxl = seg * 32 + lane;   // 0..127
        int gx = xblk + pxl;
        const float* kp = &sker[pxl >> 4][pxl & 15][t * 9];
        const float* xp = x + ((size_t)(b * TT + t) << 18);

        float w[9];
        #pragma unroll
        for (int j = 0; j < 9; j++) w[j] = kp[j];

        float o = 0.f;
        #pragma unroll
        for (int dy = 0; dy < 3; dy++) {
            int yy = y + dy - 1;
            bool yok = (yy >= 0) & (yy < HH);
            const float* row = xp + (yy << 9);
            #pragma unroll
            for (int dx = 0; dx < 3; dx++) {
                int xx = gx + dx - 1;
                bool ok = yok & (xx >= 0) & (xx < WW);
                float xv = ok ? row[xx] : 0.f;
                o = fmaf(w[dy * 3 + dx], xv, o);
            }
        }
        out[((size_t)(b * TT + t) << 18) + (y << 9) + gx] = o;
    }
}

// ---------------- launch ----------------
extern "C" void kernel_launch(void* const* d_in, const int* in_sizes, int n_in,
                              void* d_out, int out_size)
{
    const float* x_aligned = (const float*)d_in[0];
    const float* raw_diff  = (const float*)d_in[1];
    const float* w1  = (const float*)d_in[2];
    const float* g1  = (const float*)d_in[3];
    const float* b1  = (const float*)d_in[4];
    const float* rm1 = (const float*)d_in[5];
    const float* rv1 = (const float*)d_in[6];
    const float* w2  = (const float*)d_in[7];
    const float* g2  = (const float*)d_in[8];
    const float* b2  = (const float*)d_in[9];
    const float* rm2 = (const float*)d_in[10];
    const float* rv2 = (const float*)d_in[11];
    const float* w3  = (const float*)d_in[12];
    const float* g3  = (const float*)d_in[13];
    const float* b3  = (const float*)d_in[14];
    const float* rm3 = (const float*)d_in[15];
    const float* rv3 = (const float*)d_in[16];
    const float* w4  = (const float*)d_in[17];
    const float* bias = (const float*)d_in[18];
    float* out = (float*)d_out;

    const int SMEM2 = 8  * (132 * 48);   // 50,688 B
    const int SMEM4 = 12 * (136 * 48);   // 78,336 B
    static bool attr_done = false;
    if (!attr_done) {
        cudaFuncSetAttribute(conv16_hmma_kernel<2>, cudaFuncAttributeMaxDynamicSharedMemorySize, SMEM2);
        cudaFuncSetAttribute(conv16_hmma_kernel<4>, cudaFuncAttributeMaxDynamicSharedMemorySize, SMEM4);
        attr_done = true;
    }

    prep_kernel<<<1, 256>>>(w1, g1, b1, rm1, rv1, w2, g2, b2, rm2, rv2,
                            w3, g3, b3, rm3, rv3, w4);
    accum_kernel<<<NPIX / 4 / 256, 256>>>(raw_diff);
    finalize_kernel<<<1, 1>>>();
    conv1_kernel<<<NPIX / 256, 256>>>();
    {
        dim3 grd(WW / 128, HH / 64, BB);   // (4, 8, 8)
        conv16_hmma_kernel<2><<<grd, 256, SMEM2>>>();
        conv16_hmma_kernel<4><<<grd, 256, SMEM4>>>();
    }
    final_mma_kernel<<<NPIX / 128, 320>>>(x_aligned, bias, out);
}